// round 1
// baseline (speedup 1.0000x reference)
#include <cuda_runtime.h>

// Problem constants
#define NWIN   4096          // B_ = num windows * batch
#define NTOK   64            // tokens per window
#define CDIM   192           // channels
#define NHEAD  6
#define HDIM   32
#define NMASK  64            // nW
#define MROWS  (NWIN * NTOK) // 262144 token rows
#define SCALE_Q 0.17677669529663687f  // 32^-0.5

#define OUT0_ELEMS  ((size_t)MROWS * CDIM)                    // 50331648
#define ATTN_ELEMS  ((size_t)NWIN * NHEAD * NTOK * NTOK)      // 100663296

// Scratch (allocation-free: __device__ globals)
static __device__ float g_q[NWIN * NHEAD * NTOK * HDIM];   // pre-scaled by SCALE_Q
static __device__ float g_k[NWIN * NHEAD * NTOK * HDIM];
static __device__ float g_v[NWIN * NHEAD * NTOK * HDIM];
static __device__ float g_o[MROWS * CDIM];                 // [b][n][h*32+d]
static __device__ float g_bias[NHEAD * NTOK * NTOK];       // [h][n][m]

// ---------------------------------------------------------------------------
// Relative-position bias gather: bias[h][n][m] = table[relidx(n,m)*6 + h]
// ---------------------------------------------------------------------------
__global__ void bias_kernel(const float* __restrict__ table) {
    int e = blockIdx.x * 256 + threadIdx.x;          // < 6*64*64 = 24576
    int h  = e >> 12;
    int nm = e & 4095;
    int n = nm >> 6, m = nm & 63;
    int i1 = n >> 3, j1 = n & 7, i2 = m >> 3, j2 = m & 7;
    int idx = (i1 - i2 + 7) * 15 + (j1 - j2 + 7);
    g_bias[e] = table[idx * NHEAD + h];
}

// ---------------------------------------------------------------------------
// GEMM: C[m][o] = sum_c A[m][c] * W[o][c] + bias[o]
// Both A and W are K-major (K = 192). Tile 128x64, BK=16, 256 threads, 8x4/thread.
// QKV==true : A = x, scatter epilogue into g_q/g_k/g_v (q pre-scaled)
// QKV==false: A = g_o, write Cout[m*192+o]
// ---------------------------------------------------------------------------
template<bool QKV>
__global__ void __launch_bounds__(256)
gemm_kernel(const float* __restrict__ Ain, const float* __restrict__ W,
            const float* __restrict__ bias, float* __restrict__ Cout) {
    __shared__ float As[16][128];
    __shared__ float Bs[16][64];

    const float* A = QKV ? Ain : (const float*)g_o;

    const int mBase = blockIdx.y * 128;
    const int oBase = blockIdx.x * 64;
    const int tid   = threadIdx.x;
    const int rowg  = tid >> 4;   // 0..15 -> rows rowg*8..+7
    const int colg  = tid & 15;   // 0..15 -> cols colg*4..+3

    float acc[8][4];
#pragma unroll
    for (int i = 0; i < 8; i++)
#pragma unroll
        for (int j = 0; j < 4; j++) acc[i][j] = 0.0f;

    for (int k0 = 0; k0 < CDIM; k0 += 16) {
        // Load A tile 128x16 (2 float4 per thread)
#pragma unroll
        for (int i = 0; i < 2; i++) {
            int f = tid * 2 + i;
            int r = f >> 2;
            int c = (f & 3) << 2;
            float4 v = *reinterpret_cast<const float4*>(
                A + (size_t)(mBase + r) * CDIM + k0 + c);
            As[c + 0][r] = v.x; As[c + 1][r] = v.y;
            As[c + 2][r] = v.z; As[c + 3][r] = v.w;
        }
        // Load W tile 64x16 (1 float4 per thread)
        {
            int r = tid >> 2;
            int c = (tid & 3) << 2;
            float4 v = *reinterpret_cast<const float4*>(
                W + (size_t)(oBase + r) * CDIM + k0 + c);
            Bs[c + 0][r] = v.x; Bs[c + 1][r] = v.y;
            Bs[c + 2][r] = v.z; Bs[c + 3][r] = v.w;
        }
        __syncthreads();

#pragma unroll
        for (int k = 0; k < 16; k++) {
            float4 a0 = *reinterpret_cast<const float4*>(&As[k][rowg * 8]);
            float4 a1 = *reinterpret_cast<const float4*>(&As[k][rowg * 8 + 4]);
            float4 b0 = *reinterpret_cast<const float4*>(&Bs[k][colg * 4]);
            float ar[8] = {a0.x, a0.y, a0.z, a0.w, a1.x, a1.y, a1.z, a1.w};
            float br[4] = {b0.x, b0.y, b0.z, b0.w};
#pragma unroll
            for (int i = 0; i < 8; i++)
#pragma unroll
                for (int j = 0; j < 4; j++)
                    acc[i][j] += ar[i] * br[j];
        }
        __syncthreads();
    }

    // Epilogue
#pragma unroll
    for (int i = 0; i < 8; i++) {
        int m = mBase + rowg * 8 + i;
#pragma unroll
        for (int j = 0; j < 4; j++) {
            int o = oBase + colg * 4 + j;
            float val = acc[i][j] + bias[o];
            if (QKV) {
                int s  = o / CDIM;       // 0=q,1=k,2=v
                int rr = o % CDIM;
                int h  = rr >> 5;
                int d  = rr & 31;
                size_t idx = (((size_t)(m >> 6) * NHEAD + h) * NTOK + (m & 63)) * HDIM + d;
                if (s == 0)      g_q[idx] = val * SCALE_Q;
                else if (s == 1) g_k[idx] = val;
                else             g_v[idx] = val;
            } else {
                Cout[(size_t)m * CDIM + o] = val;
            }
        }
    }
}

// ---------------------------------------------------------------------------
// Attention: one block per (window b, head h). 256 threads.
// Phase 1: S = Q K^T (+bias +mask), softmax (16-lane shuffle groups)
// Phase 2: O = P V
// ---------------------------------------------------------------------------
__global__ void __launch_bounds__(256)
attn_kernel(const float* __restrict__ mask, float* __restrict__ attn_out,
            float* __restrict__ d_out_base) {
    __shared__ float Qt[32][68];   // [k][row], padded
    __shared__ float Kt[32][68];   // [k][col]
    __shared__ float Vs[64][32];   // [m][d]
    __shared__ float Pt[64][68];   // [m][row], padded

    const int b = blockIdx.x;
    const int h = blockIdx.y;
    const int tid = threadIdx.x;

    const size_t base = ((size_t)b * NHEAD + h) * (NTOK * HDIM);

    // Cooperative load of Q, K (transposed) and V (direct)
    {
        int r = tid >> 2;            // 0..63
        int p = (tid & 3) << 3;      // 0,8,16,24
        const float4* q4 = reinterpret_cast<const float4*>(g_q + base + r * HDIM + p);
        float4 v0 = q4[0], v1 = q4[1];
        Qt[p + 0][r] = v0.x; Qt[p + 1][r] = v0.y; Qt[p + 2][r] = v0.z; Qt[p + 3][r] = v0.w;
        Qt[p + 4][r] = v1.x; Qt[p + 5][r] = v1.y; Qt[p + 6][r] = v1.z; Qt[p + 7][r] = v1.w;

        const float4* k4 = reinterpret_cast<const float4*>(g_k + base + r * HDIM + p);
        v0 = k4[0]; v1 = k4[1];
        Kt[p + 0][r] = v0.x; Kt[p + 1][r] = v0.y; Kt[p + 2][r] = v0.z; Kt[p + 3][r] = v0.w;
        Kt[p + 4][r] = v1.x; Kt[p + 5][r] = v1.y; Kt[p + 6][r] = v1.z; Kt[p + 7][r] = v1.w;

        const float4* vv4 = reinterpret_cast<const float4*>(g_v + base + r * HDIM + p);
        v0 = vv4[0]; v1 = vv4[1];
        *reinterpret_cast<float4*>(&Vs[r][p])     = v0;
        *reinterpret_cast<float4*>(&Vs[r][p + 4]) = v1;
    }
    __syncthreads();

    const int rg = tid >> 4;     // 0..15
    const int cg = tid & 15;     // 0..15
    const int r0 = rg << 2;      // row tile start
    const int c0 = cg << 2;      // col tile start

    // ---- Phase 1: S = Q K^T (4x4 register tile) ----
    float acc[4][4];
#pragma unroll
    for (int i = 0; i < 4; i++)
#pragma unroll
        for (int j = 0; j < 4; j++) acc[i][j] = 0.0f;

#pragma unroll
    for (int k = 0; k < HDIM; k++) {
        float4 qv = *reinterpret_cast<const float4*>(&Qt[k][r0]);
        float4 kv = *reinterpret_cast<const float4*>(&Kt[k][c0]);
        float qa[4] = {qv.x, qv.y, qv.z, qv.w};
        float ka[4] = {kv.x, kv.y, kv.z, kv.w};
#pragma unroll
        for (int i = 0; i < 4; i++)
#pragma unroll
            for (int j = 0; j < 4; j++)
                acc[i][j] += qa[i] * ka[j];
    }

    // ---- bias + mask + softmax ----
    const float* bptr = g_bias + ((size_t)h << 12);
    const float* mptr = mask + ((size_t)(b & (NMASK - 1)) << 12);
    float p[4][4];
#pragma unroll
    for (int i = 0; i < 4; i++) {
        int rr = r0 + i;
        float4 bv = *reinterpret_cast<const float4*>(bptr + rr * NTOK + c0);
        float4 mv = *reinterpret_cast<const float4*>(mptr + rr * NTOK + c0);
        acc[i][0] += bv.x + mv.x;
        acc[i][1] += bv.y + mv.y;
        acc[i][2] += bv.z + mv.z;
        acc[i][3] += bv.w + mv.w;

        float mx = fmaxf(fmaxf(acc[i][0], acc[i][1]), fmaxf(acc[i][2], acc[i][3]));
#pragma unroll
        for (int off = 1; off < 16; off <<= 1)
            mx = fmaxf(mx, __shfl_xor_sync(0xffffffffu, mx, off));
        float s = 0.0f;
#pragma unroll
        for (int j = 0; j < 4; j++) {
            p[i][j] = __expf(acc[i][j] - mx);
            s += p[i][j];
        }
#pragma unroll
        for (int off = 1; off < 16; off <<= 1)
            s += __shfl_xor_sync(0xffffffffu, s, off);
        float inv = 1.0f / s;
#pragma unroll
        for (int j = 0; j < 4; j++) p[i][j] *= inv;
    }

    // write attn output (second output tensor)
    if (attn_out) {
        size_t abase = ((size_t)b * NHEAD + h) * (NTOK * NTOK);
#pragma unroll
        for (int i = 0; i < 4; i++) {
            *reinterpret_cast<float4*>(attn_out + abase + (size_t)(r0 + i) * NTOK + c0)
                = make_float4(p[i][0], p[i][1], p[i][2], p[i][3]);
        }
    }

    // stash P transposed for phase 2
#pragma unroll
    for (int i = 0; i < 4; i++)
#pragma unroll
        for (int j = 0; j < 4; j++)
            Pt[c0 + j][r0 + i] = p[i][j];
    __syncthreads();

    // ---- Phase 2: O = P V  (4 rows x 2 d-cols per thread) ----
    const int d0 = cg << 1;    // 0..30 step 2
    float o2[4][2];
#pragma unroll
    for (int i = 0; i < 4; i++) { o2[i][0] = 0.0f; o2[i][1] = 0.0f; }

#pragma unroll
    for (int m = 0; m < NTOK; m++) {
        float4 pv = *reinterpret_cast<const float4*>(&Pt[m][r0]);
        float2 vv = *reinterpret_cast<const float2*>(&Vs[m][d0]);
        float pa[4] = {pv.x, pv.y, pv.z, pv.w};
#pragma unroll
        for (int i = 0; i < 4; i++) {
            o2[i][0] += pa[i] * vv.x;
            o2[i][1] += pa[i] * vv.y;
        }
    }

    size_t obase = (size_t)b * NTOK * CDIM + h * HDIM + d0;
#pragma unroll
    for (int i = 0; i < 4; i++) {
        *reinterpret_cast<float2*>(&g_o[obase + (size_t)(r0 + i) * CDIM])
            = make_float2(o2[i][0], o2[i][1]);
    }
    (void)d_out_base;
}

// ---------------------------------------------------------------------------
extern "C" void kernel_launch(void* const* d_in, const int* in_sizes, int n_in,
                              void* d_out, int out_size) {
    const float* x      = (const float*)d_in[0];
    const float* mask   = (const float*)d_in[1];
    const float* qkv_w  = (const float*)d_in[2];
    const float* qkv_b  = (const float*)d_in[3];
    const float* proj_w = (const float*)d_in[4];
    const float* proj_b = (const float*)d_in[5];
    const float* table  = (const float*)d_in[6];

    float* out = (float*)d_out;
    float* attn_out = nullptr;
    if ((size_t)out_size >= OUT0_ELEMS + ATTN_ELEMS)
        attn_out = out + OUT0_ELEMS;

    // 1) relative-position bias gather
    bias_kernel<<<96, 256>>>(table);

    // 2) fused QKV projection (M=262144, O=576, K=192)
    gemm_kernel<true><<<dim3(576 / 64, MROWS / 128), 256>>>(x, qkv_w, qkv_b, nullptr);

    // 3) per-window attention (+ attn output)
    attn_kernel<<<dim3(NWIN, NHEAD), 256>>>(mask, attn_out, out);

    // 4) output projection (M=262144, O=192, K=192)
    gemm_kernel<false><<<dim3(CDIM / 64, MROWS / 128), 256>>>(nullptr, proj_w, proj_b, out);

    (void)in_sizes; (void)n_in;
}

// round 3
// speedup vs baseline: 1.8045x; 1.8045x over previous
#include <cuda_runtime.h>
#include <cuda_bf16.h>
#include <cstdint>

// Problem constants
#define NWIN   4096
#define NTOK   64
#define CDIM   192
#define NHEAD  6
#define HDIM   32
#define NMASK  64
#define MROWS  (NWIN * NTOK)          // 262144
#define SCALE_Q 0.17677669529663687f

#define OUT0_ELEMS  ((size_t)MROWS * CDIM)
#define ATTN_ELEMS  ((size_t)NWIN * NHEAD * NTOK * NTOK)

// ---------------- device scratch (allocation-free) ----------------
static __device__ float g_q[NWIN * NHEAD * NTOK * HDIM];   // pre-scaled
static __device__ float g_k[NWIN * NHEAD * NTOK * HDIM];
static __device__ float g_v[NWIN * NHEAD * NTOK * HDIM];
static __device__ float g_bias[NHEAD * NTOK * NTOK];

static __device__ __nv_bfloat16 g_xhi[MROWS * CDIM];
static __device__ __nv_bfloat16 g_xlo[MROWS * CDIM];
static __device__ __nv_bfloat16 g_ohi[MROWS * CDIM];
static __device__ __nv_bfloat16 g_olo[MROWS * CDIM];
static __device__ __nv_bfloat16 g_wq_hi[3 * CDIM * CDIM];
static __device__ __nv_bfloat16 g_wq_lo[3 * CDIM * CDIM];
static __device__ __nv_bfloat16 g_wp_hi[CDIM * CDIM];
static __device__ __nv_bfloat16 g_wp_lo[CDIM * CDIM];

// ---------------- helpers ----------------
__device__ __forceinline__ uint32_t smem_u32(const void* p) {
    uint32_t a;
    asm("{ .reg .u64 t; cvta.to.shared.u64 t, %1; cvt.u32.u64 %0, t; }" : "=r"(a) : "l"(p));
    return a;
}
__device__ __forceinline__ void ldsm4(uint32_t (&r)[4], uint32_t a) {
    asm volatile("ldmatrix.sync.aligned.m8n8.x4.shared.b16 {%0,%1,%2,%3}, [%4];"
                 : "=r"(r[0]), "=r"(r[1]), "=r"(r[2]), "=r"(r[3]) : "r"(a));
}
__device__ __forceinline__ void mma16816(float (&d)[4], const uint32_t (&a)[4],
                                         uint32_t b0, uint32_t b1) {
    asm volatile("mma.sync.aligned.m16n8k16.row.col.f32.bf16.bf16.f32 "
                 "{%0,%1,%2,%3}, {%4,%5,%6,%7}, {%8,%9}, {%0,%1,%2,%3};"
                 : "+f"(d[0]), "+f"(d[1]), "+f"(d[2]), "+f"(d[3])
                 : "r"(a[0]), "r"(a[1]), "r"(a[2]), "r"(a[3]), "r"(b0), "r"(b1));
}

// ---------------- bias gather ----------------
__global__ void bias_kernel(const float* __restrict__ table) {
    int e = blockIdx.x * 256 + threadIdx.x;
    int h  = e >> 12;
    int nm = e & 4095;
    int n = nm >> 6, m = nm & 63;
    int idx = ((n >> 3) - (m >> 3) + 7) * 15 + ((n & 7) - (m & 7) + 7);
    g_bias[e] = table[idx * NHEAD + h];
}

// ---------------- fp32 -> bf16 hi/lo split ----------------
// DST: 0 = x, 1 = qkv_w, 2 = proj_w
template<int DST>
__global__ void __launch_bounds__(256)
convert_kernel(const float* __restrict__ src, int n4) {
    int i = blockIdx.x * 256 + threadIdx.x;
    if (i >= n4) return;
    __nv_bfloat16* hi = (DST == 0) ? g_xhi : (DST == 1) ? g_wq_hi : g_wp_hi;
    __nv_bfloat16* lo = (DST == 0) ? g_xlo : (DST == 1) ? g_wq_lo : g_wp_lo;
    float4 v = reinterpret_cast<const float4*>(src)[i];
    __nv_bfloat16 h0 = __float2bfloat16(v.x);
    __nv_bfloat16 h1 = __float2bfloat16(v.y);
    __nv_bfloat16 h2 = __float2bfloat16(v.z);
    __nv_bfloat16 h3 = __float2bfloat16(v.w);
    __nv_bfloat16 l0 = __float2bfloat16(v.x - __bfloat162float(h0));
    __nv_bfloat16 l1 = __float2bfloat16(v.y - __bfloat162float(h1));
    __nv_bfloat16 l2 = __float2bfloat16(v.z - __bfloat162float(h2));
    __nv_bfloat16 l3 = __float2bfloat16(v.w - __bfloat162float(h3));
    __nv_bfloat162* hp = reinterpret_cast<__nv_bfloat162*>(hi) + i * 2;
    __nv_bfloat162* lp = reinterpret_cast<__nv_bfloat162*>(lo) + i * 2;
    hp[0] = __nv_bfloat162(h0, h1); hp[1] = __nv_bfloat162(h2, h3);
    lp[0] = __nv_bfloat162(l0, l1); lp[1] = __nv_bfloat162(l2, l3);
}

// ---------------- HMMA GEMM ----------------
// C[m][o] = sum_k A[m][k] * W[o][k] (+bias), 3-pass bf16 hi/lo split.
// CTA: 64 M x 192 N, K-chunks of 64 (3 iters). 8 warps, warp tile 32x48.
// MODE 0: A = g_x*, W = g_wq* (blockIdx.x selects q/k/v), scatter to g_q/g_k/g_v.
// MODE 1: A = g_o*, W = g_wp*, write out.
#define SMA_HI 0
#define SMA_LO 8192
#define SMB_HI 16384
#define SMB_LO 40960
#define GEMM_SMEM 65536

template<int MODE>
__global__ void __launch_bounds__(256, 2)
hmma_gemm(const float* __restrict__ bias, float* __restrict__ out) {
    extern __shared__ char sm[];
    const int tid = threadIdx.x;
    const int wid = tid >> 5, lane = tid & 31;
    const int mBase = blockIdx.y * 64;
    const int oBase = blockIdx.x * CDIM;

    const __nv_bfloat16* Agh = (MODE == 0) ? g_xhi : g_ohi;
    const __nv_bfloat16* Agl = (MODE == 0) ? g_xlo : g_olo;
    const __nv_bfloat16* Bgh = (MODE == 0) ? g_wq_hi : g_wp_hi;
    const __nv_bfloat16* Bgl = (MODE == 0) ? g_wq_lo : g_wp_lo;

    const uint32_t sb = smem_u32(sm);

    float acc[2][6][4];
#pragma unroll
    for (int a = 0; a < 2; a++)
#pragma unroll
        for (int b = 0; b < 6; b++)
#pragma unroll
            for (int c = 0; c < 4; c++) acc[a][b][c] = 0.0f;

    const int g  = lane >> 3;       // ldmatrix group
    const int rl = lane & 7;
    // A address components: row = warpM + (g&1)*8 + rl (+16 per mtile)
    const int aRow0 = (wid >> 2) * 32 + ((g & 1) << 3) + rl;
    const int aChG  = g >> 1;
    // B address components: row = warpN + (g>>1)*8 + rl (+16 per pair)
    const int bRow0 = (wid & 3) * 48 + ((g >> 1) << 3) + rl;
    const int bChG  = g & 1;

    for (int kc = 0; kc < 3; kc++) {
        // ---- load A chunk: 64 rows x 64 cols, hi+lo ----
#pragma unroll
        for (int i = 0; i < 2; i++) {
            int idx = tid + i * 256;         // 0..511
            int row = idx >> 3, ch = idx & 7;
            size_t src = (size_t)(mBase + row) * CDIM + kc * 64 + ch * 8;
            uint32_t dst = row * 128 + ((ch ^ (row & 7)) << 4);
            *reinterpret_cast<uint4*>(sm + SMA_HI + dst) =
                *reinterpret_cast<const uint4*>(Agh + src);
            *reinterpret_cast<uint4*>(sm + SMA_LO + dst) =
                *reinterpret_cast<const uint4*>(Agl + src);
        }
        // ---- load B chunk: 192 rows x 64 cols, hi+lo ----
#pragma unroll
        for (int i = 0; i < 6; i++) {
            int idx = tid + i * 256;         // 0..1535
            int row = idx >> 3, ch = idx & 7;
            size_t src = (size_t)(oBase + row) * CDIM + kc * 64 + ch * 8;
            uint32_t dst = row * 128 + ((ch ^ (row & 7)) << 4);
            *reinterpret_cast<uint4*>(sm + SMB_HI + dst) =
                *reinterpret_cast<const uint4*>(Bgh + src);
            *reinterpret_cast<uint4*>(sm + SMB_LO + dst) =
                *reinterpret_cast<const uint4*>(Bgl + src);
        }
        __syncthreads();

#pragma unroll
        for (int ap = 0; ap < 2; ap++) {                    // A = hi, lo
            const uint32_t aB = sb + (ap ? SMA_LO : SMA_HI);
#pragma unroll
            for (int ks = 0; ks < 4; ks++) {
                uint32_t af[2][4];
#pragma unroll
                for (int mt = 0; mt < 2; mt++) {
                    int row = aRow0 + mt * 16;
                    int ch  = 2 * ks + aChG;
                    ldsm4(af[mt], aB + row * 128 + ((ch ^ (row & 7)) << 4));
                }
                // B = hi always; B = lo only when A = hi
#pragma unroll
                for (int bp = 0; bp < 2; bp++) {
                    if (ap == 1 && bp == 1) break;
                    const uint32_t bB = sb + (bp ? SMB_LO : SMB_HI);
#pragma unroll
                    for (int p = 0; p < 3; p++) {
                        uint32_t bf[4];
                        int row = bRow0 + p * 16;
                        int ch  = 2 * ks + bChG;
                        ldsm4(bf, bB + row * 128 + ((ch ^ (row & 7)) << 4));
#pragma unroll
                        for (int mt = 0; mt < 2; mt++) {
                            mma16816(acc[mt][2 * p],     af[mt], bf[0], bf[1]);
                            mma16816(acc[mt][2 * p + 1], af[mt], bf[2], bf[3]);
                        }
                    }
                }
            }
        }
        __syncthreads();
    }

    // ---- epilogue ----
    const int s = blockIdx.x;                 // MODE 0: 0=q,1=k,2=v
    const float sc = (MODE == 0 && s == 0) ? SCALE_Q : 1.0f;
    float* qkv_dst = (MODE == 0) ? ((s == 0) ? g_q : (s == 1) ? g_k : g_v) : nullptr;
    const int w = blockIdx.y;                 // window id (MODE 0)

#pragma unroll
    for (int mt = 0; mt < 2; mt++) {
#pragma unroll
        for (int nt = 0; nt < 6; nt++) {
            int col = (wid & 3) * 48 + nt * 8 + (lane & 3) * 2;   // 0..191
            float b0 = bias[s * CDIM * (MODE == 0 ? 1 : 0) + col];
            float b1 = bias[s * CDIM * (MODE == 0 ? 1 : 0) + col + 1];
#pragma unroll
            for (int rh = 0; rh < 2; rh++) {
                int t = (wid >> 2) * 32 + mt * 16 + (lane >> 2) + rh * 8;  // row in CTA
                float v0 = (acc[mt][nt][2 * rh + 0] + b0) * sc;
                float v1 = (acc[mt][nt][2 * rh + 1] + b1) * sc;
                if (MODE == 0) {
                    int h = col >> 5, d = col & 31;
                    size_t di = (((size_t)w * NHEAD + h) * NTOK + t) * HDIM + d;
                    *reinterpret_cast<float2*>(qkv_dst + di) = make_float2(v0, v1);
                } else {
                    *reinterpret_cast<float2*>(out + (size_t)(mBase + t) * CDIM + col)
                        = make_float2(v0, v1);
                }
            }
        }
    }
}

// ---------------- attention (fp32), writes attn + bf16 hi/lo O ----------------
__global__ void __launch_bounds__(256)
attn_kernel(const float* __restrict__ mask, float* __restrict__ attn_out) {
    __shared__ float Qt[32][68];
    __shared__ float Kt[32][68];
    __shared__ float Vs[64][32];
    __shared__ float Pt[64][68];

    const int b = blockIdx.x;
    const int h = blockIdx.y;
    const int tid = threadIdx.x;
    const size_t base = ((size_t)b * NHEAD + h) * (NTOK * HDIM);

    {
        int r = tid >> 2;
        int p = (tid & 3) << 3;
        const float4* q4 = reinterpret_cast<const float4*>(g_q + base + r * HDIM + p);
        float4 v0 = q4[0], v1 = q4[1];
        Qt[p + 0][r] = v0.x; Qt[p + 1][r] = v0.y; Qt[p + 2][r] = v0.z; Qt[p + 3][r] = v0.w;
        Qt[p + 4][r] = v1.x; Qt[p + 5][r] = v1.y; Qt[p + 6][r] = v1.z; Qt[p + 7][r] = v1.w;
        const float4* k4 = reinterpret_cast<const float4*>(g_k + base + r * HDIM + p);
        v0 = k4[0]; v1 = k4[1];
        Kt[p + 0][r] = v0.x; Kt[p + 1][r] = v0.y; Kt[p + 2][r] = v0.z; Kt[p + 3][r] = v0.w;
        Kt[p + 4][r] = v1.x; Kt[p + 5][r] = v1.y; Kt[p + 6][r] = v1.z; Kt[p + 7][r] = v1.w;
        const float4* vv4 = reinterpret_cast<const float4*>(g_v + base + r * HDIM + p);
        v0 = vv4[0]; v1 = vv4[1];
        *reinterpret_cast<float4*>(&Vs[r][p])     = v0;
        *reinterpret_cast<float4*>(&Vs[r][p + 4]) = v1;
    }
    __syncthreads();

    const int rg = tid >> 4, cg = tid & 15;
    const int r0 = rg << 2, c0 = cg << 2;

    float acc[4][4];
#pragma unroll
    for (int i = 0; i < 4; i++)
#pragma unroll
        for (int j = 0; j < 4; j++) acc[i][j] = 0.0f;

#pragma unroll
    for (int k = 0; k < HDIM; k++) {
        float4 qv = *reinterpret_cast<const float4*>(&Qt[k][r0]);
        float4 kv = *reinterpret_cast<const float4*>(&Kt[k][c0]);
        float qa[4] = {qv.x, qv.y, qv.z, qv.w};
        float ka[4] = {kv.x, kv.y, kv.z, kv.w};
#pragma unroll
        for (int i = 0; i < 4; i++)
#pragma unroll
            for (int j = 0; j < 4; j++)
                acc[i][j] += qa[i] * ka[j];
    }

    const float* bptr = g_bias + ((size_t)h << 12);
    const float* mptr = mask + ((size_t)(b & (NMASK - 1)) << 12);
    float p[4][4];
#pragma unroll
    for (int i = 0; i < 4; i++) {
        int rr = r0 + i;
        float4 bv = *reinterpret_cast<const float4*>(bptr + rr * NTOK + c0);
        float4 mv = *reinterpret_cast<const float4*>(mptr + rr * NTOK + c0);
        acc[i][0] += bv.x + mv.x; acc[i][1] += bv.y + mv.y;
        acc[i][2] += bv.z + mv.z; acc[i][3] += bv.w + mv.w;
        float mx = fmaxf(fmaxf(acc[i][0], acc[i][1]), fmaxf(acc[i][2], acc[i][3]));
#pragma unroll
        for (int off = 1; off < 16; off <<= 1)
            mx = fmaxf(mx, __shfl_xor_sync(0xffffffffu, mx, off));
        float s = 0.0f;
#pragma unroll
        for (int j = 0; j < 4; j++) { p[i][j] = __expf(acc[i][j] - mx); s += p[i][j]; }
#pragma unroll
        for (int off = 1; off < 16; off <<= 1)
            s += __shfl_xor_sync(0xffffffffu, s, off);
        float inv = 1.0f / s;
#pragma unroll
        for (int j = 0; j < 4; j++) p[i][j] *= inv;
    }

    {
        size_t abase = ((size_t)b * NHEAD + h) * (NTOK * NTOK);
#pragma unroll
        for (int i = 0; i < 4; i++)
            *reinterpret_cast<float4*>(attn_out + abase + (size_t)(r0 + i) * NTOK + c0)
                = make_float4(p[i][0], p[i][1], p[i][2], p[i][3]);
    }

#pragma unroll
    for (int i = 0; i < 4; i++)
#pragma unroll
        for (int j = 0; j < 4; j++)
            Pt[c0 + j][r0 + i] = p[i][j];
    __syncthreads();

    const int d0 = cg << 1;
    float o2[4][2];
#pragma unroll
    for (int i = 0; i < 4; i++) { o2[i][0] = 0.0f; o2[i][1] = 0.0f; }
#pragma unroll
    for (int m = 0; m < NTOK; m++) {
        float4 pv = *reinterpret_cast<const float4*>(&Pt[m][r0]);
        float2 vv = *reinterpret_cast<const float2*>(&Vs[m][d0]);
        float pa[4] = {pv.x, pv.y, pv.z, pv.w};
#pragma unroll
        for (int i = 0; i < 4; i++) {
            o2[i][0] += pa[i] * vv.x;
            o2[i][1] += pa[i] * vv.y;
        }
    }

    size_t obase = (size_t)b * NTOK * CDIM + h * HDIM + d0;
#pragma unroll
    for (int i = 0; i < 4; i++) {
        float v0 = o2[i][0], v1 = o2[i][1];
        __nv_bfloat16 h0 = __float2bfloat16(v0);
        __nv_bfloat16 h1 = __float2bfloat16(v1);
        __nv_bfloat16 l0 = __float2bfloat16(v0 - __bfloat162float(h0));
        __nv_bfloat16 l1 = __float2bfloat16(v1 - __bfloat162float(h1));
        size_t o = obase + (size_t)(r0 + i) * CDIM;
        *reinterpret_cast<__nv_bfloat162*>(g_ohi + o) = __nv_bfloat162(h0, h1);
        *reinterpret_cast<__nv_bfloat162*>(g_olo + o) = __nv_bfloat162(l0, l1);
    }
}

// ---------------------------------------------------------------------------
extern "C" void kernel_launch(void* const* d_in, const int* in_sizes, int n_in,
                              void* d_out, int out_size) {
    const float* x      = (const float*)d_in[0];
    const float* mask   = (const float*)d_in[1];
    const float* qkv_w  = (const float*)d_in[2];
    const float* qkv_b  = (const float*)d_in[3];
    const float* proj_w = (const float*)d_in[4];
    const float* proj_b = (const float*)d_in[5];
    const float* table  = (const float*)d_in[6];

    float* out = (float*)d_out;
    float* attn_out = out + OUT0_ELEMS;

    cudaFuncSetAttribute(hmma_gemm<0>, cudaFuncAttributeMaxDynamicSharedMemorySize, GEMM_SMEM);
    cudaFuncSetAttribute(hmma_gemm<1>, cudaFuncAttributeMaxDynamicSharedMemorySize, GEMM_SMEM);

    // 1) bias gather + hi/lo conversions
    bias_kernel<<<96, 256>>>(table);
    {
        int n4 = (MROWS * CDIM) / 4;
        convert_kernel<0><<<(n4 + 255) / 256, 256>>>(x, n4);
        int w4 = (3 * CDIM * CDIM) / 4;
        convert_kernel<1><<<(w4 + 255) / 256, 256>>>(qkv_w, w4);
        int p4 = (CDIM * CDIM) / 4;
        convert_kernel<2><<<(p4 + 255) / 256, 256>>>(proj_w, p4);
    }

    // 2) QKV projection on tensor cores (blockIdx.x: 0=q,1=k,2=v)
    hmma_gemm<0><<<dim3(3, NWIN), 256, GEMM_SMEM>>>(qkv_b, nullptr);

    // 3) attention (fp32), writes attn + bf16 hi/lo O
    attn_kernel<<<dim3(NWIN, NHEAD), 256>>>(mask, attn_out);

    // 4) output projection on tensor cores
    hmma_gemm<1><<<dim3(1, NWIN), 256, GEMM_SMEM>>>(proj_b, out);

    (void)in_sizes; (void)n_in; (void)out_size;
}

// round 4
// speedup vs baseline: 2.1873x; 1.2121x over previous
#include <cuda_runtime.h>
#include <cuda_bf16.h>
#include <cstdint>

// Problem constants
#define NWIN   4096
#define NTOK   64
#define CDIM   192
#define NHEAD  6
#define HDIM   32
#define NMASK  64
#define MROWS  (NWIN * NTOK)          // 262144
#define SCALE_Q 0.17677669529663687f

#define OUT0_ELEMS  ((size_t)MROWS * CDIM)
#define ATTN_ELEMS  ((size_t)NWIN * NHEAD * NTOK * NTOK)

// ---------------- device scratch (allocation-free) ----------------
static __device__ float g_bias[NHEAD * NTOK * NTOK];

// q/k/v as bf16 hi/lo pairs, layout [b][h][tok][d]
static __device__ __nv_bfloat16 g_qhi[NWIN * NHEAD * NTOK * HDIM];
static __device__ __nv_bfloat16 g_qlo[NWIN * NHEAD * NTOK * HDIM];
static __device__ __nv_bfloat16 g_khi[NWIN * NHEAD * NTOK * HDIM];
static __device__ __nv_bfloat16 g_klo[NWIN * NHEAD * NTOK * HDIM];
static __device__ __nv_bfloat16 g_vhi[NWIN * NHEAD * NTOK * HDIM];
static __device__ __nv_bfloat16 g_vlo[NWIN * NHEAD * NTOK * HDIM];

static __device__ __nv_bfloat16 g_ohi[MROWS * CDIM];
static __device__ __nv_bfloat16 g_olo[MROWS * CDIM];
static __device__ __nv_bfloat16 g_wq_hi[3 * CDIM * CDIM];
static __device__ __nv_bfloat16 g_wq_lo[3 * CDIM * CDIM];
static __device__ __nv_bfloat16 g_wp_hi[CDIM * CDIM];
static __device__ __nv_bfloat16 g_wp_lo[CDIM * CDIM];

// ---------------- helpers ----------------
__device__ __forceinline__ uint32_t smem_u32(const void* p) {
    uint32_t a;
    asm("{ .reg .u64 t; cvta.to.shared.u64 t, %1; cvt.u32.u64 %0, t; }" : "=r"(a) : "l"(p));
    return a;
}
__device__ __forceinline__ void ldsm4(uint32_t (&r)[4], uint32_t a) {
    asm volatile("ldmatrix.sync.aligned.m8n8.x4.shared.b16 {%0,%1,%2,%3}, [%4];"
                 : "=r"(r[0]), "=r"(r[1]), "=r"(r[2]), "=r"(r[3]) : "r"(a));
}
__device__ __forceinline__ void ldsm4t(uint32_t (&r)[4], uint32_t a) {
    asm volatile("ldmatrix.sync.aligned.m8n8.x4.trans.shared.b16 {%0,%1,%2,%3}, [%4];"
                 : "=r"(r[0]), "=r"(r[1]), "=r"(r[2]), "=r"(r[3]) : "r"(a));
}
__device__ __forceinline__ void mma16816(float (&d)[4], const uint32_t (&a)[4],
                                         uint32_t b0, uint32_t b1) {
    asm volatile("mma.sync.aligned.m16n8k16.row.col.f32.bf16.bf16.f32 "
                 "{%0,%1,%2,%3}, {%4,%5,%6,%7}, {%8,%9}, {%0,%1,%2,%3};"
                 : "+f"(d[0]), "+f"(d[1]), "+f"(d[2]), "+f"(d[3])
                 : "r"(a[0]), "r"(a[1]), "r"(a[2]), "r"(a[3]), "r"(b0), "r"(b1));
}
__device__ __forceinline__ uint32_t packbf(float a, float b) {
    __nv_bfloat162 t = __floats2bfloat162_rn(a, b);   // x=a (low), y=b (high)
    return *reinterpret_cast<uint32_t*>(&t);
}
__device__ __forceinline__ void split2(float a, float b, uint32_t& hi, uint32_t& lo) {
    __nv_bfloat16 ha = __float2bfloat16(a), hb = __float2bfloat16(b);
    float ra = a - __bfloat162float(ha);
    float rb = b - __bfloat162float(hb);
    __nv_bfloat162 th; th.x = ha; th.y = hb;
    hi = *reinterpret_cast<uint32_t*>(&th);
    lo = packbf(ra, rb);
}

// ---------------- bias gather ----------------
__global__ void bias_kernel(const float* __restrict__ table) {
    int e = blockIdx.x * 256 + threadIdx.x;
    int h  = e >> 12;
    int nm = e & 4095;
    int n = nm >> 6, m = nm & 63;
    int idx = ((n >> 3) - (m >> 3) + 7) * 15 + ((n & 7) - (m & 7) + 7);
    g_bias[e] = table[idx * NHEAD + h];
}

// ---------------- fp32 -> bf16 hi/lo split (weights only) ----------------
template<int DST>   // 1 = qkv_w, 2 = proj_w
__global__ void __launch_bounds__(256)
convert_kernel(const float* __restrict__ src, int n4) {
    int i = blockIdx.x * 256 + threadIdx.x;
    if (i >= n4) return;
    __nv_bfloat16* hi = (DST == 1) ? g_wq_hi : g_wp_hi;
    __nv_bfloat16* lo = (DST == 1) ? g_wq_lo : g_wp_lo;
    float4 v = reinterpret_cast<const float4*>(src)[i];
    uint32_t h0, h1, l0, l1;
    split2(v.x, v.y, h0, l0);
    split2(v.z, v.w, h1, l1);
    reinterpret_cast<uint2*>(hi)[i] = make_uint2(h0, h1);
    reinterpret_cast<uint2*>(lo)[i] = make_uint2(l0, l1);
}

// ---------------- HMMA GEMM ----------------
// CTA: 64 M x 192 N, K-chunks of 64 (3 iters). 8 warps, warp tile 32x48.
// MODE 0: A = x (fp32, converted in-flight), W = g_wq*, write q/k/v bf16 hi/lo.
// MODE 1: A = g_ohi/olo, W = g_wp*, write out fp32.
#define SMA_HI 0
#define SMA_LO 8192
#define SMB_HI 16384
#define SMB_LO 40960
#define GEMM_SMEM 65536

template<int MODE>
__global__ void __launch_bounds__(256, 2)
hmma_gemm(const float* __restrict__ X, const float* __restrict__ bias,
          float* __restrict__ out) {
    extern __shared__ char sm[];
    const int tid = threadIdx.x;
    const int wid = tid >> 5, lane = tid & 31;
    const int mBase = blockIdx.y * 64;
    const int oBase = blockIdx.x * CDIM;

    const __nv_bfloat16* Bgh = (MODE == 0) ? g_wq_hi : g_wp_hi;
    const __nv_bfloat16* Bgl = (MODE == 0) ? g_wq_lo : g_wp_lo;

    const uint32_t sb = smem_u32(sm);

    float acc[2][6][4];
#pragma unroll
    for (int a = 0; a < 2; a++)
#pragma unroll
        for (int b = 0; b < 6; b++)
#pragma unroll
            for (int c = 0; c < 4; c++) acc[a][b][c] = 0.0f;

    const int g  = lane >> 3;
    const int rl = lane & 7;
    const int aRow0 = (wid >> 2) * 32 + ((g & 1) << 3) + rl;
    const int aChG  = g >> 1;
    const int bRow0 = (wid & 3) * 48 + ((g >> 1) << 3) + rl;
    const int bChG  = g & 1;

    for (int kc = 0; kc < 3; kc++) {
        // ---- load A chunk: 64 rows x 64 cols ----
        if (MODE == 0) {
#pragma unroll
            for (int i = 0; i < 2; i++) {
                int idx = tid + i * 256;
                int row = idx >> 3, ch = idx & 7;
                const float* src = X + (size_t)(mBase + row) * CDIM + kc * 64 + ch * 8;
                float4 f0 = *reinterpret_cast<const float4*>(src);
                float4 f1 = *reinterpret_cast<const float4*>(src + 4);
                uint32_t h0, h1, h2, h3, l0, l1, l2, l3;
                split2(f0.x, f0.y, h0, l0);
                split2(f0.z, f0.w, h1, l1);
                split2(f1.x, f1.y, h2, l2);
                split2(f1.z, f1.w, h3, l3);
                uint32_t dst = row * 128 + ((ch ^ (row & 7)) << 4);
                *reinterpret_cast<uint4*>(sm + SMA_HI + dst) = make_uint4(h0, h1, h2, h3);
                *reinterpret_cast<uint4*>(sm + SMA_LO + dst) = make_uint4(l0, l1, l2, l3);
            }
        } else {
#pragma unroll
            for (int i = 0; i < 2; i++) {
                int idx = tid + i * 256;
                int row = idx >> 3, ch = idx & 7;
                size_t src = (size_t)(mBase + row) * CDIM + kc * 64 + ch * 8;
                uint32_t dst = row * 128 + ((ch ^ (row & 7)) << 4);
                *reinterpret_cast<uint4*>(sm + SMA_HI + dst) =
                    *reinterpret_cast<const uint4*>(g_ohi + src);
                *reinterpret_cast<uint4*>(sm + SMA_LO + dst) =
                    *reinterpret_cast<const uint4*>(g_olo + src);
            }
        }
        // ---- load B chunk: 192 rows x 64 cols, hi+lo ----
#pragma unroll
        for (int i = 0; i < 6; i++) {
            int idx = tid + i * 256;
            int row = idx >> 3, ch = idx & 7;
            size_t src = (size_t)(oBase + row) * CDIM + kc * 64 + ch * 8;
            uint32_t dst = row * 128 + ((ch ^ (row & 7)) << 4);
            *reinterpret_cast<uint4*>(sm + SMB_HI + dst) =
                *reinterpret_cast<const uint4*>(Bgh + src);
            *reinterpret_cast<uint4*>(sm + SMB_LO + dst) =
                *reinterpret_cast<const uint4*>(Bgl + src);
        }
        __syncthreads();

#pragma unroll
        for (int ap = 0; ap < 2; ap++) {
            const uint32_t aB = sb + (ap ? SMA_LO : SMA_HI);
#pragma unroll
            for (int ks = 0; ks < 4; ks++) {
                uint32_t af[2][4];
#pragma unroll
                for (int mt = 0; mt < 2; mt++) {
                    int row = aRow0 + mt * 16;
                    int ch  = 2 * ks + aChG;
                    ldsm4(af[mt], aB + row * 128 + ((ch ^ (row & 7)) << 4));
                }
#pragma unroll
                for (int bp = 0; bp < 2; bp++) {
                    if (ap == 1 && bp == 1) break;
                    const uint32_t bB = sb + (bp ? SMB_LO : SMB_HI);
#pragma unroll
                    for (int p = 0; p < 3; p++) {
                        uint32_t bf[4];
                        int row = bRow0 + p * 16;
                        int ch  = 2 * ks + bChG;
                        ldsm4(bf, bB + row * 128 + ((ch ^ (row & 7)) << 4));
#pragma unroll
                        for (int mt = 0; mt < 2; mt++) {
                            mma16816(acc[mt][2 * p],     af[mt], bf[0], bf[1]);
                            mma16816(acc[mt][2 * p + 1], af[mt], bf[2], bf[3]);
                        }
                    }
                }
            }
        }
        __syncthreads();
    }

    // ---- epilogue ----
    const int s = blockIdx.x;                 // MODE 0: 0=q,1=k,2=v
    const float sc = (MODE == 0 && s == 0) ? SCALE_Q : 1.0f;
    const int w = blockIdx.y;
    __nv_bfloat16* dsth = nullptr;
    __nv_bfloat16* dstl = nullptr;
    if (MODE == 0) {
        dsth = (s == 0) ? g_qhi : (s == 1) ? g_khi : g_vhi;
        dstl = (s == 0) ? g_qlo : (s == 1) ? g_klo : g_vlo;
    }

#pragma unroll
    for (int mt = 0; mt < 2; mt++) {
#pragma unroll
        for (int nt = 0; nt < 6; nt++) {
            int col = (wid & 3) * 48 + nt * 8 + (lane & 3) * 2;
            float b0 = bias[(MODE == 0 ? s * CDIM : 0) + col];
            float b1 = bias[(MODE == 0 ? s * CDIM : 0) + col + 1];
#pragma unroll
            for (int rh = 0; rh < 2; rh++) {
                int t = (wid >> 2) * 32 + mt * 16 + (lane >> 2) + rh * 8;
                float v0 = (acc[mt][nt][2 * rh + 0] + b0) * sc;
                float v1 = (acc[mt][nt][2 * rh + 1] + b1) * sc;
                if (MODE == 0) {
                    int h = col >> 5, d = col & 31;
                    size_t di = (((size_t)w * NHEAD + h) * NTOK + t) * HDIM + d;
                    uint32_t hi, lo;
                    split2(v0, v1, hi, lo);
                    *reinterpret_cast<uint32_t*>(dsth + di) = hi;
                    *reinterpret_cast<uint32_t*>(dstl + di) = lo;
                } else {
                    *reinterpret_cast<float2*>(out + (size_t)(mBase + t) * CDIM + col)
                        = make_float2(v0, v1);
                }
            }
        }
    }
}

// ---------------- HMMA attention ----------------
// One block per (b, h), 128 threads (4 warps), warp = 16-row stripe.
// Smem: q/k/v hi/lo tiles 64x32 bf16 (4KB each, (row>>1)&3 chunk swizzle) + BM fp32.
__global__ void __launch_bounds__(128)
attn_kernel(const float* __restrict__ mask, float* __restrict__ attn_out) {
    __shared__ __align__(128) char smq[6 * 4096];
    __shared__ float BM[64][68];

    const int b = blockIdx.x, h = blockIdx.y;
    const int tid = threadIdx.x;
    const int wid = tid >> 5, lane = tid & 31;
    const int g = lane >> 3, rl = lane & 7;
    const uint32_t sb = smem_u32(smq);

    const size_t base = ((size_t)b * NHEAD + h) * (NTOK * HDIM);
#pragma unroll
    for (int i = 0; i < 2; i++) {
        int idx = tid + i * 128;
        int row = idx >> 2, c = idx & 3;
        uint32_t dst = row * 64 + ((c ^ ((row >> 1) & 3)) << 4);
        size_t src = base + row * HDIM + c * 8;
        *reinterpret_cast<uint4*>(smq + dst)         = *reinterpret_cast<const uint4*>(g_qhi + src);
        *reinterpret_cast<uint4*>(smq + 4096 + dst)  = *reinterpret_cast<const uint4*>(g_qlo + src);
        *reinterpret_cast<uint4*>(smq + 8192 + dst)  = *reinterpret_cast<const uint4*>(g_khi + src);
        *reinterpret_cast<uint4*>(smq + 12288 + dst) = *reinterpret_cast<const uint4*>(g_klo + src);
        *reinterpret_cast<uint4*>(smq + 16384 + dst) = *reinterpret_cast<const uint4*>(g_vhi + src);
        *reinterpret_cast<uint4*>(smq + 20480 + dst) = *reinterpret_cast<const uint4*>(g_vlo + src);
    }
    {
        const float* bp = g_bias + ((size_t)h << 12);
        const float* mp = mask + ((size_t)(b & (NMASK - 1)) << 12);
        for (int i = tid; i < 1024; i += 128) {
            int r = i >> 4, c = (i & 15) << 2;
            float4 bv = *reinterpret_cast<const float4*>(bp + r * 64 + c);
            float4 mv = *reinterpret_cast<const float4*>(mp + r * 64 + c);
            *reinterpret_cast<float4*>(&BM[r][c]) =
                make_float4(bv.x + mv.x, bv.y + mv.y, bv.z + mv.z, bv.w + mv.w);
        }
    }
    __syncthreads();

    // ---- S = Q K^T, 3-pass hi/lo ----
    float S[8][4];
#pragma unroll
    for (int t = 0; t < 8; t++)
#pragma unroll
        for (int j = 0; j < 4; j++) S[t][j] = 0.0f;

#pragma unroll
    for (int pass = 0; pass < 3; pass++) {
        const uint32_t qb = sb + ((pass == 2) ? 4096 : 0);
        const uint32_t kb = sb + 8192 + ((pass == 1) ? 4096 : 0);
#pragma unroll
        for (int ks = 0; ks < 2; ks++) {
            uint32_t af[4];
            {
                int row = wid * 16 + ((g & 1) << 3) + rl;
                int c = (2 * ks + (g >> 1)) ^ ((row >> 1) & 3);
                ldsm4(af, qb + row * 64 + (c << 4));
            }
#pragma unroll
            for (int nt2 = 0; nt2 < 4; nt2++) {
                uint32_t bf[4];
                {
                    int row = nt2 * 16 + ((g >> 1) << 3) + rl;
                    int c = (2 * ks + (g & 1)) ^ ((row >> 1) & 3);
                    ldsm4(bf, kb + row * 64 + (c << 4));
                }
                mma16816(S[2 * nt2],     af, bf[0], bf[1]);
                mma16816(S[2 * nt2 + 1], af, bf[2], bf[3]);
            }
        }
    }

    // ---- bias+mask, softmax on fragments ----
    const int r0 = wid * 16 + (lane >> 2);
    const int q2 = (lane & 3) * 2;
    float mlo = -1e30f, mhi = -1e30f;
#pragma unroll
    for (int t = 0; t < 8; t++) {
        float2 b0 = *reinterpret_cast<const float2*>(&BM[r0][8 * t + q2]);
        float2 b1 = *reinterpret_cast<const float2*>(&BM[r0 + 8][8 * t + q2]);
        S[t][0] += b0.x; S[t][1] += b0.y;
        S[t][2] += b1.x; S[t][3] += b1.y;
        mlo = fmaxf(mlo, fmaxf(S[t][0], S[t][1]));
        mhi = fmaxf(mhi, fmaxf(S[t][2], S[t][3]));
    }
#pragma unroll
    for (int off = 1; off < 4; off <<= 1) {
        mlo = fmaxf(mlo, __shfl_xor_sync(0xffffffffu, mlo, off));
        mhi = fmaxf(mhi, __shfl_xor_sync(0xffffffffu, mhi, off));
    }
    float slo = 0.0f, shi = 0.0f;
#pragma unroll
    for (int t = 0; t < 8; t++) {
        S[t][0] = __expf(S[t][0] - mlo); S[t][1] = __expf(S[t][1] - mlo);
        S[t][2] = __expf(S[t][2] - mhi); S[t][3] = __expf(S[t][3] - mhi);
        slo += S[t][0] + S[t][1];
        shi += S[t][2] + S[t][3];
    }
#pragma unroll
    for (int off = 1; off < 4; off <<= 1) {
        slo += __shfl_xor_sync(0xffffffffu, slo, off);
        shi += __shfl_xor_sync(0xffffffffu, shi, off);
    }
    const float ilo = 1.0f / slo, ihi = 1.0f / shi;

    // normalize, write attn, build P fragments (hi/lo)
    const size_t ab = ((size_t)b * NHEAD + h) << 12;
    uint32_t Ph[4][4], Pl[4][4];
#pragma unroll
    for (int t = 0; t < 8; t++) {
        S[t][0] *= ilo; S[t][1] *= ilo;
        S[t][2] *= ihi; S[t][3] *= ihi;
        *reinterpret_cast<float2*>(attn_out + ab + (size_t)r0 * 64 + 8 * t + q2)
            = make_float2(S[t][0], S[t][1]);
        *reinterpret_cast<float2*>(attn_out + ab + (size_t)(r0 + 8) * 64 + 8 * t + q2)
            = make_float2(S[t][2], S[t][3]);
    }
#pragma unroll
    for (int kt = 0; kt < 4; kt++) {
        split2(S[2 * kt][0],     S[2 * kt][1],     Ph[kt][0], Pl[kt][0]);
        split2(S[2 * kt][2],     S[2 * kt][3],     Ph[kt][1], Pl[kt][1]);
        split2(S[2 * kt + 1][0], S[2 * kt + 1][1], Ph[kt][2], Pl[kt][2]);
        split2(S[2 * kt + 1][2], S[2 * kt + 1][3], Ph[kt][3], Pl[kt][3]);
    }

    // ---- O = P V, 3-pass hi/lo, V via ldmatrix.trans ----
    float O[4][4];
#pragma unroll
    for (int t = 0; t < 4; t++)
#pragma unroll
        for (int j = 0; j < 4; j++) O[t][j] = 0.0f;

#pragma unroll
    for (int pass = 0; pass < 3; pass++) {
        const uint32_t vb = sb + 16384 + ((pass == 1) ? 4096 : 0);
#pragma unroll
        for (int kt = 0; kt < 4; kt++) {
            const uint32_t (&af)[4] = (pass == 2) ? Pl[kt] : Ph[kt];
#pragma unroll
            for (int nt2 = 0; nt2 < 2; nt2++) {
                uint32_t bf[4];
                int row = kt * 16 + ((g & 1) << 3) + rl;
                int c = (2 * nt2 + (g >> 1)) ^ ((row >> 1) & 3);
                ldsm4t(bf, vb + row * 64 + (c << 4));
                mma16816(O[2 * nt2],     af, bf[0], bf[1]);
                mma16816(O[2 * nt2 + 1], af, bf[2], bf[3]);
            }
        }
    }

    // ---- write O as bf16 hi/lo, layout [b][tok][h*32+d] ----
    const size_t ob = (size_t)b * NTOK * CDIM + h * HDIM;
#pragma unroll
    for (int dt = 0; dt < 4; dt++) {
        int col = 8 * dt + q2;
        uint32_t hi0, lo0, hi1, lo1;
        split2(O[dt][0], O[dt][1], hi0, lo0);
        split2(O[dt][2], O[dt][3], hi1, lo1);
        *reinterpret_cast<uint32_t*>(g_ohi + ob + (size_t)r0 * CDIM + col)       = hi0;
        *reinterpret_cast<uint32_t*>(g_olo + ob + (size_t)r0 * CDIM + col)       = lo0;
        *reinterpret_cast<uint32_t*>(g_ohi + ob + (size_t)(r0 + 8) * CDIM + col) = hi1;
        *reinterpret_cast<uint32_t*>(g_olo + ob + (size_t)(r0 + 8) * CDIM + col) = lo1;
    }
}

// ---------------------------------------------------------------------------
extern "C" void kernel_launch(void* const* d_in, const int* in_sizes, int n_in,
                              void* d_out, int out_size) {
    const float* x      = (const float*)d_in[0];
    const float* mask   = (const float*)d_in[1];
    const float* qkv_w  = (const float*)d_in[2];
    const float* qkv_b  = (const float*)d_in[3];
    const float* proj_w = (const float*)d_in[4];
    const float* proj_b = (const float*)d_in[5];
    const float* table  = (const float*)d_in[6];

    float* out = (float*)d_out;
    float* attn_out = out + OUT0_ELEMS;

    cudaFuncSetAttribute(hmma_gemm<0>, cudaFuncAttributeMaxDynamicSharedMemorySize, GEMM_SMEM);
    cudaFuncSetAttribute(hmma_gemm<1>, cudaFuncAttributeMaxDynamicSharedMemorySize, GEMM_SMEM);

    // 1) bias gather + weight hi/lo conversions (x converts fused into GEMM)
    bias_kernel<<<96, 256>>>(table);
    {
        int w4 = (3 * CDIM * CDIM) / 4;
        convert_kernel<1><<<(w4 + 255) / 256, 256>>>(qkv_w, w4);
        int p4 = (CDIM * CDIM) / 4;
        convert_kernel<2><<<(p4 + 255) / 256, 256>>>(proj_w, p4);
    }

    // 2) QKV projection (blockIdx.x: 0=q,1=k,2=v), writes bf16 hi/lo q/k/v
    hmma_gemm<0><<<dim3(3, NWIN), 256, GEMM_SMEM>>>(x, qkv_b, nullptr);

    // 3) HMMA attention: writes attn (fp32) + O (bf16 hi/lo)
    attn_kernel<<<dim3(NWIN, NHEAD), 128>>>(mask, attn_out);

    // 4) output projection
    hmma_gemm<1><<<dim3(1, NWIN), 256, GEMM_SMEM>>>(nullptr, proj_b, out);

    (void)in_sizes; (void)n_in; (void)out_size;
}

// round 5
// speedup vs baseline: 2.2353x; 1.0219x over previous
#include <cuda_runtime.h>
#include <cuda_bf16.h>
#include <cstdint>

// Problem constants
#define NWIN   4096
#define NTOK   64
#define CDIM   192
#define NHEAD  6
#define HDIM   32
#define NMASK  64
#define MROWS  (NWIN * NTOK)          // 262144
#define SCALE_Q 0.17677669529663687f

#define OUT0_ELEMS  ((size_t)MROWS * CDIM)
#define ATTN_ELEMS  ((size_t)NWIN * NHEAD * NTOK * NTOK)

// ---------------- device scratch (allocation-free) ----------------
static __device__ float g_bias[NHEAD * NTOK * NTOK];

static __device__ __nv_bfloat16 g_qhi[NWIN * NHEAD * NTOK * HDIM];
static __device__ __nv_bfloat16 g_qlo[NWIN * NHEAD * NTOK * HDIM];
static __device__ __nv_bfloat16 g_khi[NWIN * NHEAD * NTOK * HDIM];
static __device__ __nv_bfloat16 g_klo[NWIN * NHEAD * NTOK * HDIM];
static __device__ __nv_bfloat16 g_vhi[NWIN * NHEAD * NTOK * HDIM];
static __device__ __nv_bfloat16 g_vlo[NWIN * NHEAD * NTOK * HDIM];

static __device__ __nv_bfloat16 g_ohi[MROWS * CDIM];
static __device__ __nv_bfloat16 g_olo[MROWS * CDIM];
static __device__ __nv_bfloat16 g_wq_hi[3 * CDIM * CDIM];
static __device__ __nv_bfloat16 g_wq_lo[3 * CDIM * CDIM];
static __device__ __nv_bfloat16 g_wp_hi[CDIM * CDIM];
static __device__ __nv_bfloat16 g_wp_lo[CDIM * CDIM];

// ---------------- helpers ----------------
__device__ __forceinline__ uint32_t smem_u32(const void* p) {
    uint32_t a;
    asm("{ .reg .u64 t; cvta.to.shared.u64 t, %1; cvt.u32.u64 %0, t; }" : "=r"(a) : "l"(p));
    return a;
}
__device__ __forceinline__ void ldsm4(uint32_t (&r)[4], uint32_t a) {
    asm volatile("ldmatrix.sync.aligned.m8n8.x4.shared.b16 {%0,%1,%2,%3}, [%4];"
                 : "=r"(r[0]), "=r"(r[1]), "=r"(r[2]), "=r"(r[3]) : "r"(a));
}
__device__ __forceinline__ void ldsm4t(uint32_t (&r)[4], uint32_t a) {
    asm volatile("ldmatrix.sync.aligned.m8n8.x4.trans.shared.b16 {%0,%1,%2,%3}, [%4];"
                 : "=r"(r[0]), "=r"(r[1]), "=r"(r[2]), "=r"(r[3]) : "r"(a));
}
__device__ __forceinline__ void mma16816(float (&d)[4], const uint32_t (&a)[4],
                                         uint32_t b0, uint32_t b1) {
    asm volatile("mma.sync.aligned.m16n8k16.row.col.f32.bf16.bf16.f32 "
                 "{%0,%1,%2,%3}, {%4,%5,%6,%7}, {%8,%9}, {%0,%1,%2,%3};"
                 : "+f"(d[0]), "+f"(d[1]), "+f"(d[2]), "+f"(d[3])
                 : "r"(a[0]), "r"(a[1]), "r"(a[2]), "r"(a[3]), "r"(b0), "r"(b1));
}
__device__ __forceinline__ uint32_t packbf(float a, float b) {
    __nv_bfloat162 t = __floats2bfloat162_rn(a, b);
    return *reinterpret_cast<uint32_t*>(&t);
}
__device__ __forceinline__ void split2(float a, float b, uint32_t& hi, uint32_t& lo) {
    __nv_bfloat16 ha = __float2bfloat16(a), hb = __float2bfloat16(b);
    float ra = a - __bfloat162float(ha);
    float rb = b - __bfloat162float(hb);
    __nv_bfloat162 th; th.x = ha; th.y = hb;
    hi = *reinterpret_cast<uint32_t*>(&th);
    lo = packbf(ra, rb);
}
__device__ __forceinline__ void cpasync16(uint32_t dst, const void* src) {
    asm volatile("cp.async.cg.shared.global [%0], [%1], 16;" :: "r"(dst), "l"(src));
}

// ---------------- bias gather ----------------
__global__ void bias_kernel(const float* __restrict__ table) {
    int e = blockIdx.x * 256 + threadIdx.x;
    int h  = e >> 12;
    int nm = e & 4095;
    int n = nm >> 6, m = nm & 63;
    int idx = ((n >> 3) - (m >> 3) + 7) * 15 + ((n & 7) - (m & 7) + 7);
    g_bias[e] = table[idx * NHEAD + h];
}

// ---------------- fp32 -> bf16 hi/lo split (weights only) ----------------
template<int DST>   // 1 = qkv_w, 2 = proj_w
__global__ void __launch_bounds__(256)
convert_kernel(const float* __restrict__ src, int n4) {
    int i = blockIdx.x * 256 + threadIdx.x;
    if (i >= n4) return;
    __nv_bfloat16* hi = (DST == 1) ? g_wq_hi : g_wp_hi;
    __nv_bfloat16* lo = (DST == 1) ? g_wq_lo : g_wp_lo;
    float4 v = reinterpret_cast<const float4*>(src)[i];
    uint32_t h0, h1, l0, l1;
    split2(v.x, v.y, h0, l0);
    split2(v.z, v.w, h1, l1);
    reinterpret_cast<uint2*>(hi)[i] = make_uint2(h0, h1);
    reinterpret_cast<uint2*>(lo)[i] = make_uint2(l0, l1);
}

// ---------------- QKV GEMM (x read/split ONCE, cp.async B pipeline) ----------
// CTA = one window: M=64, full K=192 A tile resident; s-loop (q,k,v) x kc-loop.
// 8 warps, warp tile 32x48 over 64x192.
#define QA_HI 0
#define QA_LO 24576
#define QB    49152
#define QB_ST 49152          // per-buffer stride (hi 24576 + lo 24576)
#define QKV_SMEM (QB + 2 * QB_ST)   // 147456

__device__ __forceinline__ void qkv_issueB(uint32_t sb, int tid, int s, int kc, int buf) {
    uint32_t dstb = sb + QB + buf * QB_ST;
#pragma unroll
    for (int i = 0; i < 6; i++) {
        int idx = tid + i * 256;          // 0..1535
        int row = idx >> 3, ch = idx & 7;
        size_t src = (size_t)(s * CDIM + row) * CDIM + kc * 64 + ch * 8;
        uint32_t d = row * 128 + ((ch ^ (row & 7)) << 4);
        cpasync16(dstb + d,         g_wq_hi + src);
        cpasync16(dstb + 24576 + d, g_wq_lo + src);
    }
    asm volatile("cp.async.commit_group;" ::: "memory");
}

__global__ void __launch_bounds__(256, 1)
qkv_gemm(const float* __restrict__ X, const float* __restrict__ bias) {
    extern __shared__ char sm[];
    const uint32_t sb = smem_u32(sm);
    const int tid = threadIdx.x;
    const int wid = tid >> 5, lane = tid & 31;
    const int w = blockIdx.x;
    const int mBase = w * 64;

    // prefetch B(s=0,kc=0) so it overlaps the A load+convert
    qkv_issueB(sb, tid, 0, 0, 0);

    // load A: 64 rows x 192 fp32 -> hi/lo bf16, swizzled, once
#pragma unroll
    for (int i = 0; i < 6; i++) {
        int idx = tid + i * 256;          // 0..1535
        int row = idx / 24, cc = idx % 24;
        const float* srcp = X + (size_t)(mBase + row) * CDIM + cc * 8;
        float4 f0 = *reinterpret_cast<const float4*>(srcp);
        float4 f1 = *reinterpret_cast<const float4*>(srcp + 4);
        uint32_t h0, h1, h2, h3, l0, l1, l2, l3;
        split2(f0.x, f0.y, h0, l0);
        split2(f0.z, f0.w, h1, l1);
        split2(f1.x, f1.y, h2, l2);
        split2(f1.z, f1.w, h3, l3);
        int kc = cc >> 3, ch = cc & 7;
        uint32_t d = row * 384 + kc * 128 + ((ch ^ (row & 7)) << 4);
        *reinterpret_cast<uint4*>(sm + QA_HI + d) = make_uint4(h0, h1, h2, h3);
        *reinterpret_cast<uint4*>(sm + QA_LO + d) = make_uint4(l0, l1, l2, l3);
    }

    const int g  = lane >> 3, rl = lane & 7;
    const int aRow0 = (wid >> 2) * 32 + ((g & 1) << 3) + rl;
    const int aChG  = g >> 1;
    const int bRow0 = (wid & 3) * 48 + ((g >> 1) << 3) + rl;
    const int bChG  = g & 1;

    for (int s = 0; s < 3; s++) {
        float acc[2][6][4];
#pragma unroll
        for (int a = 0; a < 2; a++)
#pragma unroll
            for (int b2 = 0; b2 < 6; b2++)
#pragma unroll
                for (int c = 0; c < 4; c++) acc[a][b2][c] = 0.0f;

        for (int kc = 0; kc < 3; kc++) {
            int cur = s * 3 + kc;
            if (cur + 1 < 9) {
                qkv_issueB(sb, tid, (cur + 1) / 3, (cur + 1) % 3, (cur + 1) & 1);
                asm volatile("cp.async.wait_group 1;" ::: "memory");
            } else {
                asm volatile("cp.async.wait_group 0;" ::: "memory");
            }
            __syncthreads();
            const uint32_t bufb = sb + QB + (cur & 1) * QB_ST;

#pragma unroll
            for (int ap = 0; ap < 2; ap++) {
                const uint32_t aB = sb + (ap ? QA_LO : QA_HI) + kc * 128;
#pragma unroll
                for (int ks = 0; ks < 4; ks++) {
                    uint32_t af[2][4];
#pragma unroll
                    for (int mt = 0; mt < 2; mt++) {
                        int row = aRow0 + mt * 16;
                        int ch  = 2 * ks + aChG;
                        ldsm4(af[mt], aB + row * 384 + ((ch ^ (row & 7)) << 4));
                    }
#pragma unroll
                    for (int bp = 0; bp < 2; bp++) {
                        if (ap == 1 && bp == 1) break;
                        const uint32_t bB = bufb + (bp ? 24576 : 0);
#pragma unroll
                        for (int p = 0; p < 3; p++) {
                            uint32_t bf[4];
                            int row = bRow0 + p * 16;
                            int ch  = 2 * ks + bChG;
                            ldsm4(bf, bB + row * 128 + ((ch ^ (row & 7)) << 4));
#pragma unroll
                            for (int mt = 0; mt < 2; mt++) {
                                mma16816(acc[mt][2 * p],     af[mt], bf[0], bf[1]);
                                mma16816(acc[mt][2 * p + 1], af[mt], bf[2], bf[3]);
                            }
                        }
                    }
                }
            }
            __syncthreads();
        }

        // epilogue for this s
        const float sc = (s == 0) ? SCALE_Q : 1.0f;
        __nv_bfloat16* dsth = (s == 0) ? g_qhi : (s == 1) ? g_khi : g_vhi;
        __nv_bfloat16* dstl = (s == 0) ? g_qlo : (s == 1) ? g_klo : g_vlo;
#pragma unroll
        for (int mt = 0; mt < 2; mt++) {
#pragma unroll
            for (int nt = 0; nt < 6; nt++) {
                int col = (wid & 3) * 48 + nt * 8 + (lane & 3) * 2;
                float b0 = bias[s * CDIM + col];
                float b1 = bias[s * CDIM + col + 1];
#pragma unroll
                for (int rh = 0; rh < 2; rh++) {
                    int t = (wid >> 2) * 32 + mt * 16 + (lane >> 2) + rh * 8;
                    float v0 = (acc[mt][nt][2 * rh + 0] + b0) * sc;
                    float v1 = (acc[mt][nt][2 * rh + 1] + b1) * sc;
                    int h = col >> 5, d = col & 31;
                    size_t di = (((size_t)w * NHEAD + h) * NTOK + t) * HDIM + d;
                    uint32_t hi, lo;
                    split2(v0, v1, hi, lo);
                    *reinterpret_cast<uint32_t*>(dsth + di) = hi;
                    *reinterpret_cast<uint32_t*>(dstl + di) = lo;
                }
            }
        }
    }
}

// ---------------- proj GEMM (unchanged structure from R4) ----------------
#define SMA_HI 0
#define SMA_LO 8192
#define SMB_HI 16384
#define SMB_LO 40960
#define GEMM_SMEM 65536

__global__ void __launch_bounds__(256, 2)
proj_gemm(const float* __restrict__ bias, float* __restrict__ out) {
    extern __shared__ char sm[];
    const int tid = threadIdx.x;
    const int wid = tid >> 5, lane = tid & 31;
    const int mBase = blockIdx.y * 64;

    const uint32_t sb = smem_u32(sm);

    float acc[2][6][4];
#pragma unroll
    for (int a = 0; a < 2; a++)
#pragma unroll
        for (int b = 0; b < 6; b++)
#pragma unroll
            for (int c = 0; c < 4; c++) acc[a][b][c] = 0.0f;

    const int g  = lane >> 3, rl = lane & 7;
    const int aRow0 = (wid >> 2) * 32 + ((g & 1) << 3) + rl;
    const int aChG  = g >> 1;
    const int bRow0 = (wid & 3) * 48 + ((g >> 1) << 3) + rl;
    const int bChG  = g & 1;

    for (int kc = 0; kc < 3; kc++) {
#pragma unroll
        for (int i = 0; i < 2; i++) {
            int idx = tid + i * 256;
            int row = idx >> 3, ch = idx & 7;
            size_t src = (size_t)(mBase + row) * CDIM + kc * 64 + ch * 8;
            uint32_t dst = row * 128 + ((ch ^ (row & 7)) << 4);
            *reinterpret_cast<uint4*>(sm + SMA_HI + dst) =
                *reinterpret_cast<const uint4*>(g_ohi + src);
            *reinterpret_cast<uint4*>(sm + SMA_LO + dst) =
                *reinterpret_cast<const uint4*>(g_olo + src);
        }
#pragma unroll
        for (int i = 0; i < 6; i++) {
            int idx = tid + i * 256;
            int row = idx >> 3, ch = idx & 7;
            size_t src = (size_t)row * CDIM + kc * 64 + ch * 8;
            uint32_t dst = row * 128 + ((ch ^ (row & 7)) << 4);
            *reinterpret_cast<uint4*>(sm + SMB_HI + dst) =
                *reinterpret_cast<const uint4*>(g_wp_hi + src);
            *reinterpret_cast<uint4*>(sm + SMB_LO + dst) =
                *reinterpret_cast<const uint4*>(g_wp_lo + src);
        }
        __syncthreads();

#pragma unroll
        for (int ap = 0; ap < 2; ap++) {
            const uint32_t aB = sb + (ap ? SMA_LO : SMA_HI);
#pragma unroll
            for (int ks = 0; ks < 4; ks++) {
                uint32_t af[2][4];
#pragma unroll
                for (int mt = 0; mt < 2; mt++) {
                    int row = aRow0 + mt * 16;
                    int ch  = 2 * ks + aChG;
                    ldsm4(af[mt], aB + row * 128 + ((ch ^ (row & 7)) << 4));
                }
#pragma unroll
                for (int bp = 0; bp < 2; bp++) {
                    if (ap == 1 && bp == 1) break;
                    const uint32_t bB = sb + (bp ? SMB_LO : SMB_HI);
#pragma unroll
                    for (int p = 0; p < 3; p++) {
                        uint32_t bf[4];
                        int row = bRow0 + p * 16;
                        int ch  = 2 * ks + bChG;
                        ldsm4(bf, bB + row * 128 + ((ch ^ (row & 7)) << 4));
#pragma unroll
                        for (int mt = 0; mt < 2; mt++) {
                            mma16816(acc[mt][2 * p],     af[mt], bf[0], bf[1]);
                            mma16816(acc[mt][2 * p + 1], af[mt], bf[2], bf[3]);
                        }
                    }
                }
            }
        }
        __syncthreads();
    }

#pragma unroll
    for (int mt = 0; mt < 2; mt++) {
#pragma unroll
        for (int nt = 0; nt < 6; nt++) {
            int col = (wid & 3) * 48 + nt * 8 + (lane & 3) * 2;
            float b0 = bias[col];
            float b1 = bias[col + 1];
#pragma unroll
            for (int rh = 0; rh < 2; rh++) {
                int t = (wid >> 2) * 32 + mt * 16 + (lane >> 2) + rh * 8;
                float v0 = acc[mt][nt][2 * rh + 0] + b0;
                float v1 = acc[mt][nt][2 * rh + 1] + b1;
                *reinterpret_cast<float2*>(out + (size_t)(mBase + t) * CDIM + col)
                    = make_float2(v0, v1);
            }
        }
    }
}

// ---------------- HMMA attention (unchanged from R4) ----------------
__global__ void __launch_bounds__(128)
attn_kernel(const float* __restrict__ mask, float* __restrict__ attn_out) {
    __shared__ __align__(128) char smq[6 * 4096];
    __shared__ float BM[64][68];

    const int b = blockIdx.x, h = blockIdx.y;
    const int tid = threadIdx.x;
    const int wid = tid >> 5, lane = tid & 31;
    const int g = lane >> 3, rl = lane & 7;
    const uint32_t sb = smem_u32(smq);

    const size_t base = ((size_t)b * NHEAD + h) * (NTOK * HDIM);
#pragma unroll
    for (int i = 0; i < 2; i++) {
        int idx = tid + i * 128;
        int row = idx >> 2, c = idx & 3;
        uint32_t dst = row * 64 + ((c ^ ((row >> 1) & 3)) << 4);
        size_t src = base + row * HDIM + c * 8;
        *reinterpret_cast<uint4*>(smq + dst)         = *reinterpret_cast<const uint4*>(g_qhi + src);
        *reinterpret_cast<uint4*>(smq + 4096 + dst)  = *reinterpret_cast<const uint4*>(g_qlo + src);
        *reinterpret_cast<uint4*>(smq + 8192 + dst)  = *reinterpret_cast<const uint4*>(g_khi + src);
        *reinterpret_cast<uint4*>(smq + 12288 + dst) = *reinterpret_cast<const uint4*>(g_klo + src);
        *reinterpret_cast<uint4*>(smq + 16384 + dst) = *reinterpret_cast<const uint4*>(g_vhi + src);
        *reinterpret_cast<uint4*>(smq + 20480 + dst) = *reinterpret_cast<const uint4*>(g_vlo + src);
    }
    {
        const float* bp = g_bias + ((size_t)h << 12);
        const float* mp = mask + ((size_t)(b & (NMASK - 1)) << 12);
        for (int i = tid; i < 1024; i += 128) {
            int r = i >> 4, c = (i & 15) << 2;
            float4 bv = *reinterpret_cast<const float4*>(bp + r * 64 + c);
            float4 mv = *reinterpret_cast<const float4*>(mp + r * 64 + c);
            *reinterpret_cast<float4*>(&BM[r][c]) =
                make_float4(bv.x + mv.x, bv.y + mv.y, bv.z + mv.z, bv.w + mv.w);
        }
    }
    __syncthreads();

    float S[8][4];
#pragma unroll
    for (int t = 0; t < 8; t++)
#pragma unroll
        for (int j = 0; j < 4; j++) S[t][j] = 0.0f;

#pragma unroll
    for (int pass = 0; pass < 3; pass++) {
        const uint32_t qb = sb + ((pass == 2) ? 4096 : 0);
        const uint32_t kb = sb + 8192 + ((pass == 1) ? 4096 : 0);
#pragma unroll
        for (int ks = 0; ks < 2; ks++) {
            uint32_t af[4];
            {
                int row = wid * 16 + ((g & 1) << 3) + rl;
                int c = (2 * ks + (g >> 1)) ^ ((row >> 1) & 3);
                ldsm4(af, qb + row * 64 + (c << 4));
            }
#pragma unroll
            for (int nt2 = 0; nt2 < 4; nt2++) {
                uint32_t bf[4];
                {
                    int row = nt2 * 16 + ((g >> 1) << 3) + rl;
                    int c = (2 * ks + (g & 1)) ^ ((row >> 1) & 3);
                    ldsm4(bf, kb + row * 64 + (c << 4));
                }
                mma16816(S[2 * nt2],     af, bf[0], bf[1]);
                mma16816(S[2 * nt2 + 1], af, bf[2], bf[3]);
            }
        }
    }

    const int r0 = wid * 16 + (lane >> 2);
    const int q2 = (lane & 3) * 2;
    float mlo = -1e30f, mhi = -1e30f;
#pragma unroll
    for (int t = 0; t < 8; t++) {
        float2 b0 = *reinterpret_cast<const float2*>(&BM[r0][8 * t + q2]);
        float2 b1 = *reinterpret_cast<const float2*>(&BM[r0 + 8][8 * t + q2]);
        S[t][0] += b0.x; S[t][1] += b0.y;
        S[t][2] += b1.x; S[t][3] += b1.y;
        mlo = fmaxf(mlo, fmaxf(S[t][0], S[t][1]));
        mhi = fmaxf(mhi, fmaxf(S[t][2], S[t][3]));
    }
#pragma unroll
    for (int off = 1; off < 4; off <<= 1) {
        mlo = fmaxf(mlo, __shfl_xor_sync(0xffffffffu, mlo, off));
        mhi = fmaxf(mhi, __shfl_xor_sync(0xffffffffu, mhi, off));
    }
    float slo = 0.0f, shi = 0.0f;
#pragma unroll
    for (int t = 0; t < 8; t++) {
        S[t][0] = __expf(S[t][0] - mlo); S[t][1] = __expf(S[t][1] - mlo);
        S[t][2] = __expf(S[t][2] - mhi); S[t][3] = __expf(S[t][3] - mhi);
        slo += S[t][0] + S[t][1];
        shi += S[t][2] + S[t][3];
    }
#pragma unroll
    for (int off = 1; off < 4; off <<= 1) {
        slo += __shfl_xor_sync(0xffffffffu, slo, off);
        shi += __shfl_xor_sync(0xffffffffu, shi, off);
    }
    const float ilo = 1.0f / slo, ihi = 1.0f / shi;

    const size_t ab = ((size_t)b * NHEAD + h) << 12;
    uint32_t Ph[4][4], Pl[4][4];
#pragma unroll
    for (int t = 0; t < 8; t++) {
        S[t][0] *= ilo; S[t][1] *= ilo;
        S[t][2] *= ihi; S[t][3] *= ihi;
        *reinterpret_cast<float2*>(attn_out + ab + (size_t)r0 * 64 + 8 * t + q2)
            = make_float2(S[t][0], S[t][1]);
        *reinterpret_cast<float2*>(attn_out + ab + (size_t)(r0 + 8) * 64 + 8 * t + q2)
            = make_float2(S[t][2], S[t][3]);
    }
#pragma unroll
    for (int kt = 0; kt < 4; kt++) {
        split2(S[2 * kt][0],     S[2 * kt][1],     Ph[kt][0], Pl[kt][0]);
        split2(S[2 * kt][2],     S[2 * kt][3],     Ph[kt][1], Pl[kt][1]);
        split2(S[2 * kt + 1][0], S[2 * kt + 1][1], Ph[kt][2], Pl[kt][2]);
        split2(S[2 * kt + 1][2], S[2 * kt + 1][3], Ph[kt][3], Pl[kt][3]);
    }

    float O[4][4];
#pragma unroll
    for (int t = 0; t < 4; t++)
#pragma unroll
        for (int j = 0; j < 4; j++) O[t][j] = 0.0f;

#pragma unroll
    for (int pass = 0; pass < 3; pass++) {
        const uint32_t vb = sb + 16384 + ((pass == 1) ? 4096 : 0);
#pragma unroll
        for (int kt = 0; kt < 4; kt++) {
            const uint32_t (&af)[4] = (pass == 2) ? Pl[kt] : Ph[kt];
#pragma unroll
            for (int nt2 = 0; nt2 < 2; nt2++) {
                uint32_t bf[4];
                int row = kt * 16 + ((g & 1) << 3) + rl;
                int c = (2 * nt2 + (g >> 1)) ^ ((row >> 1) & 3);
                ldsm4t(bf, vb + row * 64 + (c << 4));
                mma16816(O[2 * nt2],     af, bf[0], bf[1]);
                mma16816(O[2 * nt2 + 1], af, bf[2], bf[3]);
            }
        }
    }

    const size_t ob = (size_t)b * NTOK * CDIM + h * HDIM;
#pragma unroll
    for (int dt = 0; dt < 4; dt++) {
        int col = 8 * dt + q2;
        uint32_t hi0, lo0, hi1, lo1;
        split2(O[dt][0], O[dt][1], hi0, lo0);
        split2(O[dt][2], O[dt][3], hi1, lo1);
        *reinterpret_cast<uint32_t*>(g_ohi + ob + (size_t)r0 * CDIM + col)       = hi0;
        *reinterpret_cast<uint32_t*>(g_olo + ob + (size_t)r0 * CDIM + col)       = lo0;
        *reinterpret_cast<uint32_t*>(g_ohi + ob + (size_t)(r0 + 8) * CDIM + col) = hi1;
        *reinterpret_cast<uint32_t*>(g_olo + ob + (size_t)(r0 + 8) * CDIM + col) = lo1;
    }
}

// ---------------------------------------------------------------------------
extern "C" void kernel_launch(void* const* d_in, const int* in_sizes, int n_in,
                              void* d_out, int out_size) {
    const float* x      = (const float*)d_in[0];
    const float* mask   = (const float*)d_in[1];
    const float* qkv_w  = (const float*)d_in[2];
    const float* qkv_b  = (const float*)d_in[3];
    const float* proj_w = (const float*)d_in[4];
    const float* proj_b = (const float*)d_in[5];
    const float* table  = (const float*)d_in[6];

    float* out = (float*)d_out;
    float* attn_out = out + OUT0_ELEMS;

    cudaFuncSetAttribute(qkv_gemm, cudaFuncAttributeMaxDynamicSharedMemorySize, QKV_SMEM);
    cudaFuncSetAttribute(proj_gemm, cudaFuncAttributeMaxDynamicSharedMemorySize, GEMM_SMEM);

    // 1) bias gather + weight hi/lo conversions
    bias_kernel<<<96, 256>>>(table);
    {
        int w4 = (3 * CDIM * CDIM) / 4;
        convert_kernel<1><<<(w4 + 255) / 256, 256>>>(qkv_w, w4);
        int p4 = (CDIM * CDIM) / 4;
        convert_kernel<2><<<(p4 + 255) / 256, 256>>>(proj_w, p4);
    }

    // 2) QKV projection: x read+split once per window, cp.async B pipeline
    qkv_gemm<<<NWIN, 256, QKV_SMEM>>>(x, qkv_b);

    // 3) HMMA attention: writes attn (fp32) + O (bf16 hi/lo)
    attn_kernel<<<dim3(NWIN, NHEAD), 128>>>(mask, attn_out);

    // 4) output projection
    proj_gemm<<<dim3(1, NWIN), 256, GEMM_SMEM>>>(proj_b, out);

    (void)in_sizes; (void)n_in; (void)out_size;
}

// round 6
// speedup vs baseline: 2.3146x; 1.0355x over previous
#include <cuda_runtime.h>
#include <cuda_bf16.h>
#include <cstdint>

// Problem constants
#define NWIN   4096
#define NTOK   64
#define CDIM   192
#define NHEAD  6
#define HDIM   32
#define NMASK  64
#define MROWS  (NWIN * NTOK)          // 262144
#define SCALE_Q 0.17677669529663687f

#define OUT0_ELEMS  ((size_t)MROWS * CDIM)
#define ATTN_ELEMS  ((size_t)NWIN * NHEAD * NTOK * NTOK)

// ---------------- device scratch (allocation-free) ----------------
static __device__ float g_bias[NHEAD * NTOK * NTOK];

static __device__ __nv_bfloat16 g_ohi[MROWS * CDIM];
static __device__ __nv_bfloat16 g_olo[MROWS * CDIM];
static __device__ __nv_bfloat16 g_wq_hi[3 * CDIM * CDIM];
static __device__ __nv_bfloat16 g_wq_lo[3 * CDIM * CDIM];
static __device__ __nv_bfloat16 g_wp_hi[CDIM * CDIM];
static __device__ __nv_bfloat16 g_wp_lo[CDIM * CDIM];

// ---------------- helpers ----------------
__device__ __forceinline__ uint32_t smem_u32(const void* p) {
    uint32_t a;
    asm("{ .reg .u64 t; cvta.to.shared.u64 t, %1; cvt.u32.u64 %0, t; }" : "=r"(a) : "l"(p));
    return a;
}
__device__ __forceinline__ void ldsm4(uint32_t (&r)[4], uint32_t a) {
    asm volatile("ldmatrix.sync.aligned.m8n8.x4.shared.b16 {%0,%1,%2,%3}, [%4];"
                 : "=r"(r[0]), "=r"(r[1]), "=r"(r[2]), "=r"(r[3]) : "r"(a));
}
__device__ __forceinline__ void ldsm4t(uint32_t (&r)[4], uint32_t a) {
    asm volatile("ldmatrix.sync.aligned.m8n8.x4.trans.shared.b16 {%0,%1,%2,%3}, [%4];"
                 : "=r"(r[0]), "=r"(r[1]), "=r"(r[2]), "=r"(r[3]) : "r"(a));
}
__device__ __forceinline__ void mma16816(float (&d)[4], const uint32_t (&a)[4],
                                         uint32_t b0, uint32_t b1) {
    asm volatile("mma.sync.aligned.m16n8k16.row.col.f32.bf16.bf16.f32 "
                 "{%0,%1,%2,%3}, {%4,%5,%6,%7}, {%8,%9}, {%0,%1,%2,%3};"
                 : "+f"(d[0]), "+f"(d[1]), "+f"(d[2]), "+f"(d[3])
                 : "r"(a[0]), "r"(a[1]), "r"(a[2]), "r"(a[3]), "r"(b0), "r"(b1));
}
__device__ __forceinline__ uint32_t packbf(float a, float b) {
    __nv_bfloat162 t = __floats2bfloat162_rn(a, b);
    return *reinterpret_cast<uint32_t*>(&t);
}
__device__ __forceinline__ void split2(float a, float b, uint32_t& hi, uint32_t& lo) {
    __nv_bfloat16 ha = __float2bfloat16(a), hb = __float2bfloat16(b);
    float ra = a - __bfloat162float(ha);
    float rb = b - __bfloat162float(hb);
    __nv_bfloat162 th; th.x = ha; th.y = hb;
    hi = *reinterpret_cast<uint32_t*>(&th);
    lo = packbf(ra, rb);
}
__device__ __forceinline__ void cpasync16(uint32_t dst, const void* src) {
    asm volatile("cp.async.cg.shared.global [%0], [%1], 16;" :: "r"(dst), "l"(src));
}

// ---------------- bias gather ----------------
__global__ void bias_kernel(const float* __restrict__ table) {
    int e = blockIdx.x * 256 + threadIdx.x;
    int h  = e >> 12;
    int nm = e & 4095;
    int n = nm >> 6, m = nm & 63;
    int idx = ((n >> 3) - (m >> 3) + 7) * 15 + ((n & 7) - (m & 7) + 7);
    g_bias[e] = table[idx * NHEAD + h];
}

// ---------------- fp32 -> bf16 hi/lo split (weights only) ----------------
template<int DST>   // 1 = qkv_w, 2 = proj_w
__global__ void __launch_bounds__(256)
convert_kernel(const float* __restrict__ src, int n4) {
    int i = blockIdx.x * 256 + threadIdx.x;
    if (i >= n4) return;
    __nv_bfloat16* hi = (DST == 1) ? g_wq_hi : g_wp_hi;
    __nv_bfloat16* lo = (DST == 1) ? g_wq_lo : g_wp_lo;
    float4 v = reinterpret_cast<const float4*>(src)[i];
    uint32_t h0, h1, l0, l1;
    split2(v.x, v.y, h0, l0);
    split2(v.z, v.w, h1, l1);
    reinterpret_cast<uint2*>(hi)[i] = make_uint2(h0, h1);
    reinterpret_cast<uint2*>(lo)[i] = make_uint2(l0, l1);
}

// ================== FUSED QKV + ATTENTION ==================
// One CTA per window. Smem map (bytes):
//  [0, 49152)        A hi/lo (64x192 bf16 x2)  -> reused for V hi/lo (per-head layout)
//  [49152, 122880)   B ring: 3 buffers x 24576 (hi 12288 + lo 12288), 192x32 bf16
//  [122880, 172032)  Q hi/lo (per-head layout: 6 heads x 4096 B per part)
//  [172032, 221184)  K hi/lo
#define FA_HI 0
#define FA_LO 24576
#define FB    49152
#define FB_ST 24576
#define FQ_HI 122880
#define FQ_LO 147456
#define FK_HI 172032
#define FK_LO 196608
#define FV_HI 0
#define FV_LO 24576
#define FUSED_SMEM 221184

// load W chunk (s, kk): 192 rows x 32 cols, hi+lo, chunk-swizzled 64B rows
__device__ __forceinline__ void issueB(uint32_t sb, int tid, int s, int kk, int buf) {
    uint32_t dstb = sb + FB + buf * FB_ST;
#pragma unroll
    for (int i = 0; i < 3; i++) {
        int idx = tid + i * 256;          // 0..767
        int row = idx >> 2, c = idx & 3;
        size_t src = (size_t)(s * CDIM + row) * CDIM + kk * 32 + c * 8;
        uint32_t d = dstb + row * 64 + ((c ^ ((row >> 1) & 3)) << 4);
        cpasync16(d,         g_wq_hi + src);
        cpasync16(d + 12288, g_wq_lo + src);
    }
    asm volatile("cp.async.commit_group;" ::: "memory");
}

__global__ void __launch_bounds__(256, 1)
fused_kernel(const float* __restrict__ X, const float* __restrict__ qkv_b,
             const float* __restrict__ mask, float* __restrict__ attn_out) {
    extern __shared__ char sm[];
    const uint32_t sb = smem_u32(sm);
    const int tid = threadIdx.x;
    const int wid = tid >> 5, lane = tid & 31;
    const int b = blockIdx.x;
    const int mBase = b * 64;
    const int g = lane >> 3, rl = lane & 7;

    // prefetch W chunks 0,1
    issueB(sb, tid, 0, 0, 0);
    issueB(sb, tid, 0, 1, 1);

    // load A: 64 rows x 192 fp32 -> hi/lo bf16, swizzled (3 subtiles of 64 cols)
#pragma unroll
    for (int i = 0; i < 6; i++) {
        int idx = tid + i * 256;          // 0..1535
        int row = idx / 24, cc = idx % 24;
        const float* srcp = X + (size_t)(mBase + row) * CDIM + cc * 8;
        float4 f0 = *reinterpret_cast<const float4*>(srcp);
        float4 f1 = *reinterpret_cast<const float4*>(srcp + 4);
        uint32_t h0, h1, h2, h3, l0, l1, l2, l3;
        split2(f0.x, f0.y, h0, l0);
        split2(f0.z, f0.w, h1, l1);
        split2(f1.x, f1.y, h2, l2);
        split2(f1.z, f1.w, h3, l3);
        int sub = cc >> 3, ch = cc & 7;
        uint32_t d = row * 384 + sub * 128 + ((ch ^ (row & 7)) << 4);
        *reinterpret_cast<uint4*>(sm + FA_HI + d) = make_uint4(h0, h1, h2, h3);
        *reinterpret_cast<uint4*>(sm + FA_LO + d) = make_uint4(l0, l1, l2, l3);
    }

    const int aRow0 = (wid >> 2) * 32 + ((g & 1) << 3) + rl;
    const int aChG  = g >> 1;
    const int bRow0 = (wid & 3) * 48 + ((g >> 1) << 3) + rl;
    const int bChG  = g & 1;

    float acc[2][6][4];

    // ---------------- Phase 1: QKV GEMM, 18 K32-chunks pipelined ----------------
    for (int cur = 0; cur < 18; cur++) {
        const int s = cur / 6, kk = cur % 6;
        if (kk == 0) {
#pragma unroll
            for (int a = 0; a < 2; a++)
#pragma unroll
                for (int b2 = 0; b2 < 6; b2++)
#pragma unroll
                    for (int c = 0; c < 4; c++) acc[a][b2][c] = 0.0f;
        }
        if (cur < 17) { asm volatile("cp.async.wait_group 1;" ::: "memory"); }
        else          { asm volatile("cp.async.wait_group 0;" ::: "memory"); }
        __syncthreads();
        if (cur + 2 < 18) {
            int nxt = cur + 2;
            issueB(sb, tid, nxt / 6, nxt % 6, nxt % 3);
        }
        const uint32_t bufb = sb + FB + (cur % 3) * FB_ST;
        const int sub = kk >> 1;

#pragma unroll
        for (int ap = 0; ap < 2; ap++) {
            const uint32_t aB = sb + (ap ? FA_LO : FA_HI) + sub * 128;
#pragma unroll
            for (int ks = 0; ks < 2; ks++) {
                uint32_t af[2][4];
                const int chA = 2 * ((kk & 1) * 2 + ks) + aChG;
#pragma unroll
                for (int mt = 0; mt < 2; mt++) {
                    int row = aRow0 + mt * 16;
                    ldsm4(af[mt], aB + row * 384 + ((chA ^ (row & 7)) << 4));
                }
#pragma unroll
                for (int bp = 0; bp < 2; bp++) {
                    if (ap == 1 && bp == 1) break;
                    const uint32_t bB = bufb + (bp ? 12288 : 0);
                    const int chB = 2 * ks + bChG;
#pragma unroll
                    for (int p = 0; p < 3; p++) {
                        uint32_t bf[4];
                        int row = bRow0 + p * 16;
                        ldsm4(bf, bB + row * 64 + ((chB ^ ((row >> 1) & 3)) << 4));
#pragma unroll
                        for (int mt = 0; mt < 2; mt++) {
                            mma16816(acc[mt][2 * p],     af[mt], bf[0], bf[1]);
                            mma16816(acc[mt][2 * p + 1], af[mt], bf[2], bf[3]);
                        }
                    }
                }
            }
        }

        if (kk == 5) {
            // epilogue: write this s's 64x192 result into smem per-head layout
            if (s == 2) __syncthreads();    // all warps done reading A before V overwrites it
            const float sc = (s == 0) ? SCALE_Q : 1.0f;
            const uint32_t dh = (s == 0) ? FQ_HI : (s == 1) ? FK_HI : FV_HI;
            const uint32_t dl = (s == 0) ? FQ_LO : (s == 1) ? FK_LO : FV_LO;
#pragma unroll
            for (int mt = 0; mt < 2; mt++) {
#pragma unroll
                for (int nt = 0; nt < 6; nt++) {
                    int col = (wid & 3) * 48 + nt * 8 + (lane & 3) * 2;
                    float b0 = qkv_b[s * CDIM + col];
                    float b1 = qkv_b[s * CDIM + col + 1];
                    int hh = col >> 5, d = col & 31;
#pragma unroll
                    for (int rh = 0; rh < 2; rh++) {
                        int t = (wid >> 2) * 32 + mt * 16 + (lane >> 2) + rh * 8;
                        float v0 = (acc[mt][nt][2 * rh + 0] + b0) * sc;
                        float v1 = (acc[mt][nt][2 * rh + 1] + b1) * sc;
                        uint32_t hi, lo;
                        split2(v0, v1, hi, lo);
                        uint32_t off = hh * 4096 + t * 64 +
                                       (((d >> 3) ^ ((t >> 1) & 3)) << 4) + (d & 7) * 2;
                        *reinterpret_cast<uint32_t*>(sm + dh + off) = hi;
                        *reinterpret_cast<uint32_t*>(sm + dl + off) = lo;
                    }
                }
            }
        }
    }
    __syncthreads();

    // ---------------- Phase 2: attention, 2 heads per iteration ----------------
    const int wid4 = tid >> 5 & 3;
    const int r0 = wid4 * 16 + (lane >> 2);
    const int q2 = (lane & 3) * 2;
    const float* mp = mask + ((size_t)(b & (NMASK - 1)) << 12);

    for (int it = 0; it < 3; it++) {
        const int h = 2 * it + (wid >> 2);
        const uint32_t qoff = h * 4096;

        // S = Q K^T, 3-pass hi/lo
        float S[8][4];
#pragma unroll
        for (int t = 0; t < 8; t++)
#pragma unroll
            for (int j = 0; j < 4; j++) S[t][j] = 0.0f;

#pragma unroll
        for (int pass = 0; pass < 3; pass++) {
            const uint32_t qb = sb + ((pass == 2) ? FQ_LO : FQ_HI) + qoff;
            const uint32_t kb = sb + ((pass == 1) ? FK_LO : FK_HI) + qoff;
#pragma unroll
            for (int ks = 0; ks < 2; ks++) {
                uint32_t af[4];
                {
                    int row = wid4 * 16 + ((g & 1) << 3) + rl;
                    int c = (2 * ks + (g >> 1)) ^ ((row >> 1) & 3);
                    ldsm4(af, qb + row * 64 + (c << 4));
                }
#pragma unroll
                for (int nt2 = 0; nt2 < 4; nt2++) {
                    uint32_t bf[4];
                    {
                        int row = nt2 * 16 + ((g >> 1) << 3) + rl;
                        int c = (2 * ks + (g & 1)) ^ ((row >> 1) & 3);
                        ldsm4(bf, kb + row * 64 + (c << 4));
                    }
                    mma16816(S[2 * nt2],     af, bf[0], bf[1]);
                    mma16816(S[2 * nt2 + 1], af, bf[2], bf[3]);
                }
            }
        }

        // bias + mask (direct from L2) + softmax on fragments
        const float* bp = g_bias + ((size_t)h << 12);
        float mlo = -1e30f, mhi = -1e30f;
#pragma unroll
        for (int t = 0; t < 8; t++) {
            int cc = 8 * t + q2;
            float2 b0 = *reinterpret_cast<const float2*>(bp + r0 * 64 + cc);
            float2 b1 = *reinterpret_cast<const float2*>(bp + (r0 + 8) * 64 + cc);
            float2 m0 = *reinterpret_cast<const float2*>(mp + r0 * 64 + cc);
            float2 m1 = *reinterpret_cast<const float2*>(mp + (r0 + 8) * 64 + cc);
            S[t][0] += b0.x + m0.x; S[t][1] += b0.y + m0.y;
            S[t][2] += b1.x + m1.x; S[t][3] += b1.y + m1.y;
            mlo = fmaxf(mlo, fmaxf(S[t][0], S[t][1]));
            mhi = fmaxf(mhi, fmaxf(S[t][2], S[t][3]));
        }
#pragma unroll
        for (int off = 1; off < 4; off <<= 1) {
            mlo = fmaxf(mlo, __shfl_xor_sync(0xffffffffu, mlo, off));
            mhi = fmaxf(mhi, __shfl_xor_sync(0xffffffffu, mhi, off));
        }
        float slo = 0.0f, shi = 0.0f;
#pragma unroll
        for (int t = 0; t < 8; t++) {
            S[t][0] = __expf(S[t][0] - mlo); S[t][1] = __expf(S[t][1] - mlo);
            S[t][2] = __expf(S[t][2] - mhi); S[t][3] = __expf(S[t][3] - mhi);
            slo += S[t][0] + S[t][1];
            shi += S[t][2] + S[t][3];
        }
#pragma unroll
        for (int off = 1; off < 4; off <<= 1) {
            slo += __shfl_xor_sync(0xffffffffu, slo, off);
            shi += __shfl_xor_sync(0xffffffffu, shi, off);
        }
        const float ilo = 1.0f / slo, ihi = 1.0f / shi;

        // normalize, write attn, build P fragments (hi/lo)
        const size_t ab = ((size_t)b * NHEAD + h) << 12;
        uint32_t Ph[4][4], Pl[4][4];
#pragma unroll
        for (int t = 0; t < 8; t++) {
            S[t][0] *= ilo; S[t][1] *= ilo;
            S[t][2] *= ihi; S[t][3] *= ihi;
            *reinterpret_cast<float2*>(attn_out + ab + (size_t)r0 * 64 + 8 * t + q2)
                = make_float2(S[t][0], S[t][1]);
            *reinterpret_cast<float2*>(attn_out + ab + (size_t)(r0 + 8) * 64 + 8 * t + q2)
                = make_float2(S[t][2], S[t][3]);
        }
#pragma unroll
        for (int kt = 0; kt < 4; kt++) {
            split2(S[2 * kt][0],     S[2 * kt][1],     Ph[kt][0], Pl[kt][0]);
            split2(S[2 * kt][2],     S[2 * kt][3],     Ph[kt][1], Pl[kt][1]);
            split2(S[2 * kt + 1][0], S[2 * kt + 1][1], Ph[kt][2], Pl[kt][2]);
            split2(S[2 * kt + 1][2], S[2 * kt + 1][3], Ph[kt][3], Pl[kt][3]);
        }

        // O = P V, 3-pass hi/lo, V via ldmatrix.trans (V lives in old A region)
        float O[4][4];
#pragma unroll
        for (int t = 0; t < 4; t++)
#pragma unroll
            for (int j = 0; j < 4; j++) O[t][j] = 0.0f;

#pragma unroll
        for (int pass = 0; pass < 3; pass++) {
            const uint32_t vb = sb + ((pass == 1) ? FV_LO : FV_HI) + qoff;
#pragma unroll
            for (int kt = 0; kt < 4; kt++) {
                const uint32_t (&af)[4] = (pass == 2) ? Pl[kt] : Ph[kt];
#pragma unroll
                for (int nt2 = 0; nt2 < 2; nt2++) {
                    uint32_t bf[4];
                    int row = kt * 16 + ((g & 1) << 3) + rl;
                    int c = (2 * nt2 + (g >> 1)) ^ ((row >> 1) & 3);
                    ldsm4t(bf, vb + row * 64 + (c << 4));
                    mma16816(O[2 * nt2],     af, bf[0], bf[1]);
                    mma16816(O[2 * nt2 + 1], af, bf[2], bf[3]);
                }
            }
        }

        // write O as bf16 hi/lo, layout [b][tok][h*32+d]
        const size_t ob = (size_t)b * NTOK * CDIM + h * HDIM;
#pragma unroll
        for (int dt = 0; dt < 4; dt++) {
            int col = 8 * dt + q2;
            uint32_t hi0, lo0, hi1, lo1;
            split2(O[dt][0], O[dt][1], hi0, lo0);
            split2(O[dt][2], O[dt][3], hi1, lo1);
            *reinterpret_cast<uint32_t*>(g_ohi + ob + (size_t)r0 * CDIM + col)       = hi0;
            *reinterpret_cast<uint32_t*>(g_olo + ob + (size_t)r0 * CDIM + col)       = lo0;
            *reinterpret_cast<uint32_t*>(g_ohi + ob + (size_t)(r0 + 8) * CDIM + col) = hi1;
            *reinterpret_cast<uint32_t*>(g_olo + ob + (size_t)(r0 + 8) * CDIM + col) = lo1;
        }
    }
}

// ---------------- proj GEMM (unchanged from R5) ----------------
#define SMA_HI 0
#define SMA_LO 8192
#define SMB_HI 16384
#define SMB_LO 40960
#define GEMM_SMEM 65536

__global__ void __launch_bounds__(256, 2)
proj_gemm(const float* __restrict__ bias, float* __restrict__ out) {
    extern __shared__ char sm[];
    const int tid = threadIdx.x;
    const int wid = tid >> 5, lane = tid & 31;
    const int mBase = blockIdx.y * 64;

    const uint32_t sb = smem_u32(sm);

    float acc[2][6][4];
#pragma unroll
    for (int a = 0; a < 2; a++)
#pragma unroll
        for (int b = 0; b < 6; b++)
#pragma unroll
            for (int c = 0; c < 4; c++) acc[a][b][c] = 0.0f;

    const int g  = lane >> 3, rl = lane & 7;
    const int aRow0 = (wid >> 2) * 32 + ((g & 1) << 3) + rl;
    const int aChG  = g >> 1;
    const int bRow0 = (wid & 3) * 48 + ((g >> 1) << 3) + rl;
    const int bChG  = g & 1;

    for (int kc = 0; kc < 3; kc++) {
#pragma unroll
        for (int i = 0; i < 2; i++) {
            int idx = tid + i * 256;
            int row = idx >> 3, ch = idx & 7;
            size_t src = (size_t)(mBase + row) * CDIM + kc * 64 + ch * 8;
            uint32_t dst = row * 128 + ((ch ^ (row & 7)) << 4);
            *reinterpret_cast<uint4*>(sm + SMA_HI + dst) =
                *reinterpret_cast<const uint4*>(g_ohi + src);
            *reinterpret_cast<uint4*>(sm + SMA_LO + dst) =
                *reinterpret_cast<const uint4*>(g_olo + src);
        }
#pragma unroll
        for (int i = 0; i < 6; i++) {
            int idx = tid + i * 256;
            int row = idx >> 3, ch = idx & 7;
            size_t src = (size_t)row * CDIM + kc * 64 + ch * 8;
            uint32_t dst = row * 128 + ((ch ^ (row & 7)) << 4);
            *reinterpret_cast<uint4*>(sm + SMB_HI + dst) =
                *reinterpret_cast<const uint4*>(g_wp_hi + src);
            *reinterpret_cast<uint4*>(sm + SMB_LO + dst) =
                *reinterpret_cast<const uint4*>(g_wp_lo + src);
        }
        __syncthreads();

#pragma unroll
        for (int ap = 0; ap < 2; ap++) {
            const uint32_t aB = sb + (ap ? SMA_LO : SMA_HI);
#pragma unroll
            for (int ks = 0; ks < 4; ks++) {
                uint32_t af[2][4];
#pragma unroll
                for (int mt = 0; mt < 2; mt++) {
                    int row = aRow0 + mt * 16;
                    int ch  = 2 * ks + aChG;
                    ldsm4(af[mt], aB + row * 128 + ((ch ^ (row & 7)) << 4));
                }
#pragma unroll
                for (int bp = 0; bp < 2; bp++) {
                    if (ap == 1 && bp == 1) break;
                    const uint32_t bB = sb + (bp ? SMB_LO : SMB_HI);
#pragma unroll
                    for (int p = 0; p < 3; p++) {
                        uint32_t bf[4];
                        int row = bRow0 + p * 16;
                        int ch  = 2 * ks + bChG;
                        ldsm4(bf, bB + row * 128 + ((ch ^ (row & 7)) << 4));
#pragma unroll
                        for (int mt = 0; mt < 2; mt++) {
                            mma16816(acc[mt][2 * p],     af[mt], bf[0], bf[1]);
                            mma16816(acc[mt][2 * p + 1], af[mt], bf[2], bf[3]);
                        }
                    }
                }
            }
        }
        __syncthreads();
    }

#pragma unroll
    for (int mt = 0; mt < 2; mt++) {
#pragma unroll
        for (int nt = 0; nt < 6; nt++) {
            int col = (wid & 3) * 48 + nt * 8 + (lane & 3) * 2;
            float b0 = bias[col];
            float b1 = bias[col + 1];
#pragma unroll
            for (int rh = 0; rh < 2; rh++) {
                int t = (wid >> 2) * 32 + mt * 16 + (lane >> 2) + rh * 8;
                float v0 = acc[mt][nt][2 * rh + 0] + b0;
                float v1 = acc[mt][nt][2 * rh + 1] + b1;
                *reinterpret_cast<float2*>(out + (size_t)(mBase + t) * CDIM + col)
                    = make_float2(v0, v1);
            }
        }
    }
}

// ---------------------------------------------------------------------------
extern "C" void kernel_launch(void* const* d_in, const int* in_sizes, int n_in,
                              void* d_out, int out_size) {
    const float* x      = (const float*)d_in[0];
    const float* mask   = (const float*)d_in[1];
    const float* qkv_w  = (const float*)d_in[2];
    const float* qkv_b  = (const float*)d_in[3];
    const float* proj_w = (const float*)d_in[4];
    const float* proj_b = (const float*)d_in[5];
    const float* table  = (const float*)d_in[6];

    float* out = (float*)d_out;
    float* attn_out = out + OUT0_ELEMS;

    cudaFuncSetAttribute(fused_kernel, cudaFuncAttributeMaxDynamicSharedMemorySize, FUSED_SMEM);
    cudaFuncSetAttribute(proj_gemm, cudaFuncAttributeMaxDynamicSharedMemorySize, GEMM_SMEM);

    // 1) bias gather + weight hi/lo conversions
    bias_kernel<<<96, 256>>>(table);
    {
        int w4 = (3 * CDIM * CDIM) / 4;
        convert_kernel<1><<<(w4 + 255) / 256, 256>>>(qkv_w, w4);
        int p4 = (CDIM * CDIM) / 4;
        convert_kernel<2><<<(p4 + 255) / 256, 256>>>(proj_w, p4);
    }

    // 2) fused QKV + attention: writes attn (fp32) + O (bf16 hi/lo)
    fused_kernel<<<NWIN, 256, FUSED_SMEM>>>(x, qkv_b, mask, attn_out);

    // 3) output projection
    proj_gemm<<<dim3(1, NWIN), 256, GEMM_SMEM>>>(proj_b, out);

    (void)in_sizes; (void)n_in; (void)out_size;
}